// round 12
// baseline (speedup 1.0000x reference)
#include <cuda_runtime.h>
#include <cuda_bf16.h>
#include <cstdint>

// ---------------------------------------------------------------------------
// roi_grid_head, round 11: 2 CTAs/SM (two independent barrier domains).
// BM=128 x BN=96, 256 threads (8 warps, 4m x 2n, warp tile 32x48 — same
// per-warp structure as the proven R8 core), 3-stage cp.async, bf16 hi/lo
// 3-stream mma.sync (D = Ahi*Bhi + Ahi*Blo + Alo*Bhi), staged epilogue.
// ---------------------------------------------------------------------------

#define NROI   512
#define CIN0   256
#define OHW    7
#define PIX    49
#define NCO    576
#define NP     9
#define NC     64
#define NREST  7
#define KG0    (CIN0 * 9)            // 2304
#define KGR    (NCO * 9)             // 5184
#define MTOT   (NROI * PIX)          // 25088 = 196*128
#define NGROUP 36
#define GSZ    784
#define HALF_OUT (NROI * NCO * PIX)  // 14450688

#define BM 128
#define BN 96
#define BK 32
#define SSTR 40                       // smem row stride in bf16 units (80B)
#define NSTAGE 3

// __device__ scratch (zero-initialized; padded border pixels never written)
__device__ unsigned short g_acth[NROI * 81 * NCO];    // [n][9x9 pad][576]
__device__ unsigned short g_actl[NROI * 81 * NCO];
__device__ unsigned short g_x0h[NROI * 256 * CIN0];   // [n][16x16 pad][256]
__device__ unsigned short g_x0l[NROI * 256 * CIN0];
__device__ unsigned short g_w0h[NCO * KG0];           // [co][tap*256+ci]
__device__ unsigned short g_w0l[NCO * KG0];
__device__ unsigned short g_wrh[NREST * NCO * KGR];   // [l][co][tap*576+ci]
__device__ unsigned short g_wrl[NREST * NCO * KGR];
__device__ float g_bufA[HALF_OUT];
__device__ float g_bufB[HALF_OUT];

__constant__ int c_esrc[24]   = {1,3, 0,2,4, 1,5, 0,4,6, 1,3,5,7, 2,4,8, 3,7, 4,6,8, 5,7};
__constant__ int c_estart[10] = {0,2,5,7,10,14,17,19,22,24};

// ---------------------------------------------------------------------------
__device__ __forceinline__ void split_bf(float f, unsigned short& h, unsigned short& l) {
    __nv_bfloat16 bh = __float2bfloat16(f);
    float r = f - __bfloat162float(bh);
    h = __bfloat16_as_ushort(bh);
    l = __bfloat16_as_ushort(__float2bfloat16(r));
}

__device__ __forceinline__ void mma_bf16(float& c0, float& c1, float& c2, float& c3,
                                         uint32_t a0, uint32_t a1, uint32_t a2, uint32_t a3,
                                         uint32_t b0, uint32_t b1) {
    asm volatile(
        "mma.sync.aligned.m16n8k16.row.col.f32.bf16.bf16.f32 "
        "{%0,%1,%2,%3},{%4,%5,%6,%7},{%8,%9},{%0,%1,%2,%3};\n"
        : "+f"(c0), "+f"(c1), "+f"(c2), "+f"(c3)
        : "r"(a0), "r"(a1), "r"(a2), "r"(a3), "r"(b0), "r"(b1));
}

__device__ __forceinline__ void ldmx4(uint32_t& r0, uint32_t& r1, uint32_t& r2, uint32_t& r3,
                                      uint32_t addr) {
    asm volatile("ldmatrix.sync.aligned.m8n8.x4.shared.b16 {%0,%1,%2,%3},[%4];\n"
                 : "=r"(r0), "=r"(r1), "=r"(r2), "=r"(r3) : "r"(addr));
}

__device__ __forceinline__ void cp16(uint32_t daddr, const void* src) {
    asm volatile("cp.async.cg.shared.global [%0], [%1], 16;\n" :: "r"(daddr), "l"(src));
}
__device__ __forceinline__ void cp_commit() { asm volatile("cp.async.commit_group;\n" ::: "memory"); }
__device__ __forceinline__ void cp_wait1()  { asm volatile("cp.async.wait_group 1;\n" ::: "memory"); }

// ---------------------------------------------------------------------------
// Packing kernels
// ---------------------------------------------------------------------------
__global__ void __launch_bounds__(256) pack_x0_kernel(const float* __restrict__ x) {
    __shared__ float sx[32 * 196];
    const int n  = blockIdx.x;
    const int c0 = blockIdx.y * 32;
    const int tid = threadIdx.x;
    for (int idx = tid; idx < 32 * 196; idx += 256) {
        int c = idx / 196, pix = idx - c * 196;
        sx[idx] = x[((size_t)(n * CIN0 + c0 + c)) * 196 + pix];
    }
    __syncthreads();
    for (int idx = tid; idx < 196 * 32; idx += 256) {
        int pix = idx >> 5, cl = idx & 31;
        int y = pix / 14, xx = pix - y * 14;
        unsigned short h, l;
        split_bf(sx[cl * 196 + pix], h, l);
        size_t o = ((size_t)(n * 256) + (y + 1) * 16 + (xx + 1)) * CIN0 + c0 + cl;
        g_x0h[o] = h; g_x0l[o] = l;
    }
}

__global__ void __launch_bounds__(256) pack_w0_kernel(const float* __restrict__ w) {
    int i = blockIdx.x * 256 + threadIdx.x;       // NCO*KG0
    int co = i / KG0, r = i - co * KG0;
    int tap = r / CIN0, ci = r - tap * CIN0;
    unsigned short h, l;
    split_bf(w[(size_t)(co * CIN0 + ci) * 9 + tap], h, l);
    g_w0h[i] = h; g_w0l[i] = l;
}

__global__ void __launch_bounds__(256) pack_wr_kernel(const float* __restrict__ w) {
    int i = blockIdx.x * 256 + threadIdx.x;       // NREST*NCO*KGR
    const int per = NCO * KGR;
    int lyr = i / per, rr = i - lyr * per;
    int co = rr / KGR, r = rr - co * KGR;
    int tap = r / NCO, ci = r - tap * NCO;
    unsigned short h, l;
    split_bf(w[((size_t)(lyr * NCO + co) * NCO + ci) * 9 + tap], h, l);
    g_wrh[i] = h; g_wrl[i] = l;
}

// ---------------------------------------------------------------------------
// NHWC implicit-GEMM conv: out[m][co] = sum_k A[m][k]*B[co][k],
// k = tap*CPT + ci, A gathered from padded NHWC planes.
// BM=128 BN=96 BK=32, 256 threads (8 warps, 4m x 2n, warp tile 32x48),
// 3-stage cp.async, 2 CTAs/SM, hi/lo 3-stream mma, staged epilogue.
// ---------------------------------------------------------------------------
template<int CPT, int PITCH, int S, int K>
__global__ void __launch_bounds__(256, 2) conv_gemm_kernel(
    const unsigned short* __restrict__ Ah, const unsigned short* __restrict__ Al,
    const unsigned short* __restrict__ Bgh, const unsigned short* __restrict__ Bgl,
    const float* __restrict__ bias, float* __restrict__ out)
{
    extern __shared__ unsigned short smem[];
    constexpr int A_SZ  = BM * SSTR;              // 5120 u16
    constexpr int B_SZ  = BN * SSTR;              // 3840 u16
    constexpr int STG   = 2 * A_SZ + 2 * B_SZ;    // 17920 u16 = 35840 B
    constexpr int T     = K / BK;
    constexpr int CPT32 = CPT / BK;
    constexpr int NPIXP = PITCH * PITCH;

    const int tid  = threadIdx.x;
    const int lane = tid & 31;
    const int warp = tid >> 5;
    const int wm = warp >> 1, wn = warp & 1;      // 4 x 2 warp grid
    const int grp = lane >> 2, tg = lane & 3;
    const int co0 = blockIdx.x * BN;
    const int m0  = blockIdx.y * BM;

    const uint32_t smem_b = (uint32_t)__cvta_generic_to_shared(smem);

    // A loader: 128 rows x 2 chunks(16 u16): ar = tid>>1, ac = (tid&1)*16
    const int ar = tid >> 1;
    const int ac = (tid & 1) * 16;
    const int am   = m0 + ar;
    const int nimg = am / PIX;
    const int apix = am - nimg * PIX;
    const int ay   = apix / OHW, ax = apix - ay * OHW;
    const unsigned short* rowH = Ah + ((size_t)nimg * NPIXP
                                       + (size_t)(S * ay) * PITCH + (S * ax)) * CPT;
    const unsigned short* rowL = Al + ((size_t)nimg * NPIXP
                                       + (size_t)(S * ay) * PITCH + (S * ax)) * CPT;
    const uint32_t sAo = (uint32_t)(ar * SSTR * 2);

    // B loader: 96 rows x 4 segs(8 u16) = 384 slots; slot0 = tid, slot1 = tid+256 (tid<128)
    const int br0  = tid >> 2;                    // 0..63
    const int br1  = 64 + (tid >> 2);             // 64..95 (valid when tid<128)
    const int bseg = (tid & 3) * 8;
    const bool b1on = (tid < 128);
    const unsigned short* pBh0 = Bgh + (size_t)(co0 + br0) * K + bseg;
    const unsigned short* pBl0 = Bgl + (size_t)(co0 + br0) * K + bseg;
    const unsigned short* pBh1 = Bgh + (size_t)(co0 + br1) * K + bseg;
    const unsigned short* pBl1 = Bgl + (size_t)(co0 + br1) * K + bseg;
    const uint32_t sBo0 = (uint32_t)((br0 * SSTR + bseg) * 2);
    const uint32_t sBo1 = (uint32_t)((br1 * SSTR + bseg) * 2);

    // ldmatrix per-thread byte offsets within plane
    const uint32_t offA = (uint32_t)(((wm * 32 + (lane & 15)) * SSTR + 8 * (lane >> 4)) * 2);
    const uint32_t offB = (uint32_t)(((wn * 48 + (lane & 7) + 8 * (lane >> 4)) * SSTR
                                      + 8 * ((lane >> 3) & 1)) * 2);

    float acc[2][6][4];
#pragma unroll
    for (int a = 0; a < 2; a++)
#pragma unroll
        for (int b = 0; b < 6; b++)
#pragma unroll
            for (int c = 0; c < 4; c++) acc[a][b][c] = 0.f;

#define ISSUE(t_)                                                              \
    do {                                                                       \
        int t__ = (t_);                                                        \
        if (t__ < T) {                                                         \
            const uint32_t sb = smem_b + (uint32_t)((t__ % 3) * STG) * 2;      \
            const int tap__ = t__ / CPT32;                                     \
            const int rem__ = t__ - tap__ * CPT32;                             \
            const int ky__  = tap__ / 3;                                       \
            const int kx__  = tap__ - ky__ * 3;                                \
            const int poff__ = (ky__ * PITCH + kx__) * CPT + rem__ * BK + ac;  \
            cp16(sb + sAo + ac * 2,            rowH + poff__);                 \
            cp16(sb + sAo + (ac + 8) * 2,      rowH + poff__ + 8);             \
            cp16(sb + A_SZ * 2 + sAo + ac * 2,       rowL + poff__);           \
            cp16(sb + A_SZ * 2 + sAo + (ac + 8) * 2, rowL + poff__ + 8);       \
            const int kt__ = t__ * BK;                                         \
            cp16(sb + 2 * A_SZ * 2 + sBo0,          pBh0 + kt__);              \
            cp16(sb + (2 * A_SZ + B_SZ) * 2 + sBo0, pBl0 + kt__);              \
            if (b1on) {                                                        \
                cp16(sb + 2 * A_SZ * 2 + sBo1,          pBh1 + kt__);          \
                cp16(sb + (2 * A_SZ + B_SZ) * 2 + sBo1, pBl1 + kt__);          \
            }                                                                  \
        }                                                                      \
        cp_commit();                                                           \
    } while (0)

    ISSUE(0);
    ISSUE(1);

    for (int t = 0; t < T; t++) {
        cp_wait1();
        __syncthreads();
        ISSUE(t + 2);

        const uint32_t aH = smem_b + (uint32_t)((t % 3) * STG) * 2;
        const uint32_t aL = aH + A_SZ * 2;
        const uint32_t bH = aH + 2 * A_SZ * 2;
        const uint32_t bL = bH + B_SZ * 2;

#pragma unroll
        for (int h = 0; h < BK; h += 16) {
            uint32_t Af[2][4], Lf[2][4], Bf[6][2], Mf[6][2];

            // ---- stream 1: A_hi, B_hi loads, then hi*hi mmas ----
#pragma unroll
            for (int mi = 0; mi < 2; mi++) {
                const uint32_t d = offA + (uint32_t)((mi * 16 * SSTR + h) * 2);
                ldmx4(Af[mi][0], Af[mi][1], Af[mi][2], Af[mi][3], aH + d);
            }
#pragma unroll
            for (int np = 0; np < 3; np++) {
                const uint32_t d = offB + (uint32_t)((np * 16 * SSTR + h) * 2);
                ldmx4(Bf[2*np][0], Bf[2*np][1], Bf[2*np+1][0], Bf[2*np+1][1], bH + d);
            }
#pragma unroll
            for (int mi = 0; mi < 2; mi++)
#pragma unroll
                for (int ni = 0; ni < 6; ni++)
                    mma_bf16(acc[mi][ni][0], acc[mi][ni][1], acc[mi][ni][2], acc[mi][ni][3],
                             Af[mi][0], Af[mi][1], Af[mi][2], Af[mi][3],
                             Bf[ni][0], Bf[ni][1]);

            // ---- stream 2: B_lo loads overlap, then hi*lo mmas ----
#pragma unroll
            for (int np = 0; np < 3; np++) {
                const uint32_t d = offB + (uint32_t)((np * 16 * SSTR + h) * 2);
                ldmx4(Mf[2*np][0], Mf[2*np][1], Mf[2*np+1][0], Mf[2*np+1][1], bL + d);
            }
#pragma unroll
            for (int mi = 0; mi < 2; mi++)
#pragma unroll
                for (int ni = 0; ni < 6; ni++)
                    mma_bf16(acc[mi][ni][0], acc[mi][ni][1], acc[mi][ni][2], acc[mi][ni][3],
                             Af[mi][0], Af[mi][1], Af[mi][2], Af[mi][3],
                             Mf[ni][0], Mf[ni][1]);

            // ---- stream 3: A_lo loads overlap, then lo*hi mmas ----
#pragma unroll
            for (int mi = 0; mi < 2; mi++) {
                const uint32_t d = offA + (uint32_t)((mi * 16 * SSTR + h) * 2);
                ldmx4(Lf[mi][0], Lf[mi][1], Lf[mi][2], Lf[mi][3], aL + d);
            }
#pragma unroll
            for (int mi = 0; mi < 2; mi++)
#pragma unroll
                for (int ni = 0; ni < 6; ni++)
                    mma_bf16(acc[mi][ni][0], acc[mi][ni][1], acc[mi][ni][2], acc[mi][ni][3],
                             Lf[mi][0], Lf[mi][1], Lf[mi][2], Lf[mi][3],
                             Bf[ni][0], Bf[ni][1]);
        }
    }
#undef ISSUE

    // ---- epilogue: stage acc in smem, then coalesced NCHW writes ----
    __syncthreads();                 // all compute done; smem free for reuse
    float* sOut = reinterpret_cast<float*>(smem);   // [co][129] padded, 49.5 KB
#pragma unroll
    for (int mi = 0; mi < 2; mi++) {
#pragma unroll
        for (int half = 0; half < 2; half++) {
            int ml = wm * 32 + mi * 16 + grp + 8 * half;
#pragma unroll
            for (int ni = 0; ni < 6; ni++) {
                int cl = wn * 48 + ni * 8 + 2 * tg;
                sOut[cl * 129 + ml]       = acc[mi][ni][2 * half];
                sOut[(cl + 1) * 129 + ml] = acc[mi][ni][2 * half + 1];
            }
        }
    }
    __syncthreads();
    for (int idx = tid; idx < BN * BM; idx += 256) {
        int cl = idx >> 7;            // 0..95
        int ml = idx & 127;           // consecutive m for consecutive tid
        int m  = m0 + ml;
        int nimg2 = m / PIX;
        int pix2  = m - nimg2 * PIX;
        int co = co0 + cl;
        out[((size_t)nimg2 * NCO + co) * PIX + pix2] = sOut[cl * 129 + ml] + __ldg(&bias[co]);
    }
}

// ---------------------------------------------------------------------------
// GroupNorm + affine + ReLU (in-place fp32 NCHW) + NHWC hi/lo repack.
// ---------------------------------------------------------------------------
__global__ void __launch_bounds__(256) gn_relu_pack_kernel(
    float* __restrict__ buf, const float* __restrict__ sc, const float* __restrict__ bi,
    unsigned short* __restrict__ ph, unsigned short* __restrict__ pl)
{
    const int blk = blockIdx.x;
    const int n   = blk / NGROUP;
    const int g   = blk - n * NGROUP;
    float* base = buf + (size_t)blk * GSZ;
    const int tid = threadIdx.x;

    __shared__ float s_vals[GSZ];
    __shared__ float r1[8], r2[8];
    __shared__ float s_mu, s_inv;

    float vals[4];
    int cnt = 0;
    float s1 = 0.f, s2 = 0.f;
    for (int e = tid; e < GSZ; e += 256) {
        float x = base[e];
        vals[cnt++] = x;
        s1 += x; s2 += x * x;
    }
#pragma unroll
    for (int o = 16; o > 0; o >>= 1) {
        s1 += __shfl_xor_sync(0xffffffff, s1, o);
        s2 += __shfl_xor_sync(0xffffffff, s2, o);
    }
    const int w = tid >> 5, lane = tid & 31;
    if (lane == 0) { r1[w] = s1; r2[w] = s2; }
    __syncthreads();
    if (tid == 0) {
        float a = 0.f, b = 0.f;
#pragma unroll
        for (int i = 0; i < 8; i++) { a += r1[i]; b += r2[i]; }
        float mu  = a * (1.f / GSZ);
        float var = b * (1.f / GSZ) - mu * mu;
        s_mu = mu;
        s_inv = rsqrtf(var + 1e-5f);
    }
    __syncthreads();
    const float mu = s_mu, inv = s_inv;
    cnt = 0;
    for (int e = tid; e < GSZ; e += 256) {
        const int chl = e / PIX;
        const int ch  = g * 16 + chl;
        float y = (vals[cnt++] - mu) * inv * sc[ch] + bi[ch];
        y = fmaxf(y, 0.f);
        base[e] = y;
        s_vals[e] = y;
    }
    __syncthreads();

    if (tid < PIX) {
        const int py = tid / OHW, px = tid - py * OHW;
        uint32_t hw[8], lw[8];
#pragma unroll
        for (int j = 0; j < 8; j++) {
            unsigned short h0, l0, h1, l1;
            split_bf(s_vals[(2 * j) * PIX + tid], h0, l0);
            split_bf(s_vals[(2 * j + 1) * PIX + tid], h1, l1);
            hw[j] = (uint32_t)h0 | ((uint32_t)h1 << 16);
            lw[j] = (uint32_t)l0 | ((uint32_t)l1 << 16);
        }
        size_t o = ((size_t)(n * 81) + (py + 1) * 9 + (px + 1)) * NCO + g * 16;
        *(uint4*)(ph + o)     = make_uint4(hw[0], hw[1], hw[2], hw[3]);
        *(uint4*)(ph + o + 8) = make_uint4(hw[4], hw[5], hw[6], hw[7]);
        *(uint4*)(pl + o)     = make_uint4(lw[0], lw[1], lw[2], lw[3]);
        *(uint4*)(pl + o + 8) = make_uint4(lw[4], lw[5], lw[6], lw[7]);
    }
}

// ---------------------------------------------------------------------------
// Message passing, dst-major (unchanged).
// ---------------------------------------------------------------------------
__global__ void __launch_bounds__(256) msg_pass_kernel(
    const float* __restrict__ src_feat, const float* __restrict__ pts,
    const float* __restrict__ dw_w, const float* __restrict__ dw_b,
    const float* __restrict__ pw_w, const float* __restrict__ pw_b,
    float* __restrict__ outp)
{
    const int n = blockIdx.x;
    const int p = blockIdx.y;
    const int tid = threadIdx.x;

    __shared__ float s_in[NC * PIX];
    __shared__ float s_dw[NC * PIX];
    __shared__ float s_pw[NC * NC];

    float racc[13];
    const float* ptsb = pts + (size_t)(n * NCO + p * NC) * PIX;
#pragma unroll
    for (int k = 0; k < 13; k++) {
        int i = tid + k * 256;
        if (i < NC * PIX) racc[k] = ptsb[i];
    }

    const int e0 = c_estart[p], e1 = c_estart[p + 1];
    for (int ed = e0; ed < e1; ed++) {
        const int q = c_esrc[ed];
        const float* sb = src_feat + (size_t)(n * NCO + q * NC) * PIX;
        for (int i = tid; i < NC * PIX; i += 256) s_in[i] = sb[i];
        for (int i = tid; i < NC * NC; i += 256) s_pw[i] = pw_w[ed * NC * NC + i];
        __syncthreads();

        for (int i = tid; i < NC * PIX; i += 256) {
            const int c = i / PIX;
            const int pix = i - c * PIX;
            const int y = pix / OHW, x = pix - y * OHW;
            const float* wv = dw_w + (ed * NC + c) * 25;
            float a = dw_b[ed * NC + c];
#pragma unroll
            for (int dy = 0; dy < 5; dy++) {
                const int yy = y + dy - 2;
                if ((unsigned)yy < (unsigned)OHW) {
#pragma unroll
                    for (int dx = 0; dx < 5; dx++) {
                        const int xx = x + dx - 2;
                        if ((unsigned)xx < (unsigned)OHW)
                            a += wv[dy * 5 + dx] * s_in[c * PIX + yy * OHW + xx];
                    }
                }
            }
            s_dw[i] = a;
        }
        __syncthreads();

#pragma unroll
        for (int k = 0; k < 13; k++) {
            const int i = tid + k * 256;
            if (i < NC * PIX) {
                const int o = i / PIX;
                const int pix = i - o * PIX;
                float a = pw_b[ed * NC + o];
                const float* wr = &s_pw[o * NC];
#pragma unroll 8
                for (int ic = 0; ic < NC; ic++) a += wr[ic] * s_dw[ic * PIX + pix];
                racc[k] += a;
            }
        }
        __syncthreads();
    }

    float* ob = outp + (size_t)(n * NCO + p * NC) * PIX;
#pragma unroll
    for (int k = 0; k < 13; k++) {
        int i = tid + k * 256;
        if (i < NC * PIX) ob[i] = racc[k];
    }
}

__global__ void __launch_bounds__(256) copy_kernel(
    const float* __restrict__ s, float* __restrict__ d)
{
    int i = blockIdx.x * 256 + threadIdx.x;
    d[i] = s[i];
}

// ---------------------------------------------------------------------------
extern "C" void kernel_launch(void* const* d_in, const int* in_sizes, int n_in,
                              void* d_out, int out_size)
{
    const float* x       = (const float*)d_in[0];
    const float* conv0_w = (const float*)d_in[1];
    const float* conv0_b = (const float*)d_in[2];
    const float* gn0_s   = (const float*)d_in[3];
    const float* gn0_b   = (const float*)d_in[4];
    const float* convs_w = (const float*)d_in[5];
    const float* convs_b = (const float*)d_in[6];
    const float* gns_s   = (const float*)d_in[7];
    const float* gns_b   = (const float*)d_in[8];
    const float* fo_dw_w = (const float*)d_in[9];
    const float* fo_dw_b = (const float*)d_in[10];
    const float* fo_pw_w = (const float*)d_in[11];
    const float* fo_pw_b = (const float*)d_in[12];
    const float* so_dw_w = (const float*)d_in[13];
    const float* so_dw_b = (const float*)d_in[14];
    const float* so_pw_w = (const float*)d_in[15];
    const float* so_pw_b = (const float*)d_in[16];
    float* out = (float*)d_out;

    float *pA, *pB;
    unsigned short *pActH, *pActL, *pX0H, *pX0L, *pW0H, *pW0L, *pWrH, *pWrL;
    cudaGetSymbolAddress((void**)&pA,    g_bufA);
    cudaGetSymbolAddress((void**)&pB,    g_bufB);
    cudaGetSymbolAddress((void**)&pActH, g_acth);
    cudaGetSymbolAddress((void**)&pActL, g_actl);
    cudaGetSymbolAddress((void**)&pX0H,  g_x0h);
    cudaGetSymbolAddress((void**)&pX0L,  g_x0l);
    cudaGetSymbolAddress((void**)&pW0H,  g_w0h);
    cudaGetSymbolAddress((void**)&pW0L,  g_w0l);
    cudaGetSymbolAddress((void**)&pWrH,  g_wrh);
    cudaGetSymbolAddress((void**)&pWrL,  g_wrl);

    const int SMEM_CONV = NSTAGE * (2 * BM * SSTR + 2 * BN * SSTR) * 2;   // 107520 B
    cudaFuncSetAttribute((const void*)conv_gemm_kernel<CIN0, 16, 2, KG0>,
                         cudaFuncAttributeMaxDynamicSharedMemorySize, SMEM_CONV);
    cudaFuncSetAttribute((const void*)conv_gemm_kernel<NCO, 9, 1, KGR>,
                         cudaFuncAttributeMaxDynamicSharedMemorySize, SMEM_CONV);

    // 1) pack inputs & weights (NHWC / tap-major)
    pack_x0_kernel<<<dim3(NROI, CIN0 / 32), 256>>>(x);
    pack_w0_kernel<<<(NCO * KG0) / 256, 256>>>(conv0_w);
    pack_wr_kernel<<<(NREST * NCO * KGR) / 256, 256>>>(convs_w);

    dim3 cgrid(NCO / BN, MTOT / BM);   // (6, 196): co fastest -> A L2 reuse

    // 2) conv0 (stride 2) + GN0/ReLU(+repack)
    conv_gemm_kernel<CIN0, 16, 2, KG0><<<cgrid, 256, SMEM_CONV>>>(
        pX0H, pX0L, pW0H, pW0L, conv0_b, pA);
    gn_relu_pack_kernel<<<NROI * NGROUP, 256>>>(pA, gn0_s, gn0_b, pActH, pActL);

    // 3) 7x [conv + GN/ReLU(+repack)], ping-pong
    float* cur = pA;
    float* nxt = pB;
    for (int l = 0; l < NREST; l++) {
        conv_gemm_kernel<NCO, 9, 1, KGR><<<cgrid, 256, SMEM_CONV>>>(
            pActH, pActL, pWrH + (size_t)l * NCO * KGR, pWrL + (size_t)l * NCO * KGR,
            convs_b + l * NCO, nxt);
        gn_relu_pack_kernel<<<NROI * NGROUP, 256>>>(nxt, gns_s + l * NCO, gns_b + l * NCO,
                                                    pActH, pActL);
        float* t = cur; cur = nxt; nxt = t;
    }
    // cur == final h, nxt free

    // 4) output half 1: h
    copy_kernel<<<HALF_OUT / 256, 256>>>(cur, out);

    // 5) first-order fusion -> nxt
    dim3 mgrid(NROI, NP);
    msg_pass_kernel<<<mgrid, 256>>>(cur, cur, fo_dw_w, fo_dw_b, fo_pw_w, fo_pw_b, nxt);

    // 6) second-order fusion -> output half 2
    msg_pass_kernel<<<mgrid, 256>>>(nxt, cur, so_dw_w, so_dw_b, so_pw_w, so_pw_b,
                                    out + HALF_OUT);
}

// round 13
// speedup vs baseline: 1.0594x; 1.0594x over previous
#include <cuda_runtime.h>
#include <cuda_bf16.h>
#include <cstdint>

// ---------------------------------------------------------------------------
// roi_grid_head, round 12: R9 core with BK=64 (half the k-stage boundaries),
// 2-stage double buffer. BM=128 x BN=192, 512 thr, 4m x 4n warps (32x48),
// bf16 hi/lo 3-stream mma.sync (D = Ahi*Bhi + Ahi*Blo + Alo*Bhi),
// staged coalesced epilogue.
// ---------------------------------------------------------------------------

#define NROI   512
#define CIN0   256
#define OHW    7
#define PIX    49
#define NCO    576
#define NP     9
#define NC     64
#define NREST  7
#define KG0    (CIN0 * 9)            // 2304
#define KGR    (NCO * 9)             // 5184
#define MTOT   (NROI * PIX)          // 25088 = 196*128
#define NGROUP 36
#define GSZ    784
#define HALF_OUT (NROI * NCO * PIX)  // 14450688

#define BM 128
#define BN 192
#define BK 64
#define SSTR 72                       // smem row stride in bf16 units (144B)

// __device__ scratch (zero-initialized; padded border pixels never written)
__device__ unsigned short g_acth[NROI * 81 * NCO];    // [n][9x9 pad][576]
__device__ unsigned short g_actl[NROI * 81 * NCO];
__device__ unsigned short g_x0h[NROI * 256 * CIN0];   // [n][16x16 pad][256]
__device__ unsigned short g_x0l[NROI * 256 * CIN0];
__device__ unsigned short g_w0h[NCO * KG0];           // [co][tap*256+ci]
__device__ unsigned short g_w0l[NCO * KG0];
__device__ unsigned short g_wrh[NREST * NCO * KGR];   // [l][co][tap*576+ci]
__device__ unsigned short g_wrl[NREST * NCO * KGR];
__device__ float g_bufA[HALF_OUT];
__device__ float g_bufB[HALF_OUT];

__constant__ int c_esrc[24]   = {1,3, 0,2,4, 1,5, 0,4,6, 1,3,5,7, 2,4,8, 3,7, 4,6,8, 5,7};
__constant__ int c_estart[10] = {0,2,5,7,10,14,17,19,22,24};

// ---------------------------------------------------------------------------
__device__ __forceinline__ void split_bf(float f, unsigned short& h, unsigned short& l) {
    __nv_bfloat16 bh = __float2bfloat16(f);
    float r = f - __bfloat162float(bh);
    h = __bfloat16_as_ushort(bh);
    l = __bfloat16_as_ushort(__float2bfloat16(r));
}

__device__ __forceinline__ void mma_bf16(float& c0, float& c1, float& c2, float& c3,
                                         uint32_t a0, uint32_t a1, uint32_t a2, uint32_t a3,
                                         uint32_t b0, uint32_t b1) {
    asm volatile(
        "mma.sync.aligned.m16n8k16.row.col.f32.bf16.bf16.f32 "
        "{%0,%1,%2,%3},{%4,%5,%6,%7},{%8,%9},{%0,%1,%2,%3};\n"
        : "+f"(c0), "+f"(c1), "+f"(c2), "+f"(c3)
        : "r"(a0), "r"(a1), "r"(a2), "r"(a3), "r"(b0), "r"(b1));
}

__device__ __forceinline__ void ldmx4(uint32_t& r0, uint32_t& r1, uint32_t& r2, uint32_t& r3,
                                      uint32_t addr) {
    asm volatile("ldmatrix.sync.aligned.m8n8.x4.shared.b16 {%0,%1,%2,%3},[%4];\n"
                 : "=r"(r0), "=r"(r1), "=r"(r2), "=r"(r3) : "r"(addr));
}

__device__ __forceinline__ void cp16(uint32_t daddr, const void* src) {
    asm volatile("cp.async.cg.shared.global [%0], [%1], 16;\n" :: "r"(daddr), "l"(src));
}
__device__ __forceinline__ void cp_commit() { asm volatile("cp.async.commit_group;\n" ::: "memory"); }
__device__ __forceinline__ void cp_wait1()  { asm volatile("cp.async.wait_group 1;\n" ::: "memory"); }

// ---------------------------------------------------------------------------
// Packing kernels
// ---------------------------------------------------------------------------
__global__ void __launch_bounds__(256) pack_x0_kernel(const float* __restrict__ x) {
    __shared__ float sx[32 * 196];
    const int n  = blockIdx.x;
    const int c0 = blockIdx.y * 32;
    const int tid = threadIdx.x;
    for (int idx = tid; idx < 32 * 196; idx += 256) {
        int c = idx / 196, pix = idx - c * 196;
        sx[idx] = x[((size_t)(n * CIN0 + c0 + c)) * 196 + pix];
    }
    __syncthreads();
    for (int idx = tid; idx < 196 * 32; idx += 256) {
        int pix = idx >> 5, cl = idx & 31;
        int y = pix / 14, xx = pix - y * 14;
        unsigned short h, l;
        split_bf(sx[cl * 196 + pix], h, l);
        size_t o = ((size_t)(n * 256) + (y + 1) * 16 + (xx + 1)) * CIN0 + c0 + cl;
        g_x0h[o] = h; g_x0l[o] = l;
    }
}

__global__ void __launch_bounds__(256) pack_w0_kernel(const float* __restrict__ w) {
    int i = blockIdx.x * 256 + threadIdx.x;       // NCO*KG0
    int co = i / KG0, r = i - co * KG0;
    int tap = r / CIN0, ci = r - tap * CIN0;
    unsigned short h, l;
    split_bf(w[(size_t)(co * CIN0 + ci) * 9 + tap], h, l);
    g_w0h[i] = h; g_w0l[i] = l;
}

__global__ void __launch_bounds__(256) pack_wr_kernel(const float* __restrict__ w) {
    int i = blockIdx.x * 256 + threadIdx.x;       // NREST*NCO*KGR
    const int per = NCO * KGR;
    int lyr = i / per, rr = i - lyr * per;
    int co = rr / KGR, r = rr - co * KGR;
    int tap = r / NCO, ci = r - tap * NCO;
    unsigned short h, l;
    split_bf(w[((size_t)(lyr * NCO + co) * NCO + ci) * 9 + tap], h, l);
    g_wrh[i] = h; g_wrl[i] = l;
}

// ---------------------------------------------------------------------------
// NHWC implicit-GEMM conv: out[m][co] = sum_k A[m][k]*B[co][k],
// k = tap*CPT + ci, A gathered from padded NHWC planes.
// BM=128 BN=192 BK=64, 512 threads (16 warps, 4m x 4n, warp tile 32x48),
// 2-stage cp.async double buffer, hi/lo 3-stream mma, staged epilogue.
// ---------------------------------------------------------------------------
template<int CPT, int PITCH, int S, int K>
__global__ void __launch_bounds__(512, 1) conv_gemm_kernel(
    const unsigned short* __restrict__ Ah, const unsigned short* __restrict__ Al,
    const unsigned short* __restrict__ Bgh, const unsigned short* __restrict__ Bgl,
    const float* __restrict__ bias, float* __restrict__ out)
{
    extern __shared__ unsigned short smem[];
    constexpr int A_SZ  = BM * SSTR;              // 9216 u16
    constexpr int B_SZ  = BN * SSTR;              // 13824 u16
    constexpr int STG   = 2 * A_SZ + 2 * B_SZ;    // 46080 u16 = 92160 B
    constexpr int T     = K / BK;
    constexpr int CPT64 = CPT / BK;
    constexpr int NPIXP = PITCH * PITCH;

    const int tid  = threadIdx.x;
    const int lane = tid & 31;
    const int warp = tid >> 5;
    const int wm = warp >> 2, wn = warp & 3;      // 4 x 4 warp grid
    const int grp = lane >> 2, tg = lane & 3;
    const int co0 = blockIdx.x * BN;
    const int m0  = blockIdx.y * BM;

    const uint32_t smem_b = (uint32_t)__cvta_generic_to_shared(smem);

    // A loader: 128 rows x 8 chunks(16B); thread covers 2 consecutive chunks.
    const int ar  = tid >> 2;                     // 0..127
    const int ach = (tid & 3) * 16;               // u16 offset {0,16,32,48}
    const int am   = m0 + ar;
    const int nimg = am / PIX;
    const int apix = am - nimg * PIX;
    const int ay   = apix / OHW, ax = apix - ay * OHW;
    const unsigned short* rowH = Ah + ((size_t)nimg * NPIXP
                                       + (size_t)(S * ay) * PITCH + (S * ax)) * CPT;
    const unsigned short* rowL = Al + ((size_t)nimg * NPIXP
                                       + (size_t)(S * ay) * PITCH + (S * ax)) * CPT;
    const uint32_t sAo = (uint32_t)((ar * SSTR + ach) * 2);

    // B loader: 192 rows x 8 chunks = 1536 slots; slots tid, tid+512, tid+1024
    int brj[3], bcj[3];
    uint32_t sBoj[3];
#pragma unroll
    for (int j = 0; j < 3; j++) {
        int slot = tid + j * 512;
        brj[j] = slot >> 3;                       // 0..191
        bcj[j] = (slot & 7) * 8;                  // u16 offset
        sBoj[j] = (uint32_t)((brj[j] * SSTR + bcj[j]) * 2);
    }
    const unsigned short* pBh0 = Bgh + (size_t)(co0 + brj[0]) * K + bcj[0];
    const unsigned short* pBl0 = Bgl + (size_t)(co0 + brj[0]) * K + bcj[0];
    const unsigned short* pBh1 = Bgh + (size_t)(co0 + brj[1]) * K + bcj[1];
    const unsigned short* pBl1 = Bgl + (size_t)(co0 + brj[1]) * K + bcj[1];
    const unsigned short* pBh2 = Bgh + (size_t)(co0 + brj[2]) * K + bcj[2];
    const unsigned short* pBl2 = Bgl + (size_t)(co0 + brj[2]) * K + bcj[2];

    // ldmatrix per-thread byte offsets within plane
    const uint32_t offA = (uint32_t)(((wm * 32 + (lane & 15)) * SSTR + 8 * (lane >> 4)) * 2);
    const uint32_t offB = (uint32_t)(((wn * 48 + (lane & 7) + 8 * (lane >> 4)) * SSTR
                                      + 8 * ((lane >> 3) & 1)) * 2);

    float acc[2][6][4];
#pragma unroll
    for (int a = 0; a < 2; a++)
#pragma unroll
        for (int b = 0; b < 6; b++)
#pragma unroll
            for (int c = 0; c < 4; c++) acc[a][b][c] = 0.f;

#define ISSUE(t_)                                                              \
    do {                                                                       \
        int t__ = (t_);                                                        \
        if (t__ < T) {                                                         \
            const uint32_t sb = smem_b + (uint32_t)((t__ & 1) * STG) * 2;      \
            const int tap__ = t__ / CPT64;                                     \
            const int rem__ = t__ - tap__ * CPT64;                             \
            const int ky__  = tap__ / 3;                                       \
            const int kx__  = tap__ - ky__ * 3;                                \
            const int poff__ = (ky__ * PITCH + kx__) * CPT + rem__ * BK + ach; \
            cp16(sb + sAo,                rowH + poff__);                      \
            cp16(sb + sAo + 16,           rowH + poff__ + 8);                  \
            cp16(sb + A_SZ * 2 + sAo,      rowL + poff__);                     \
            cp16(sb + A_SZ * 2 + sAo + 16, rowL + poff__ + 8);                 \
            const int kt__ = t__ * BK;                                         \
            cp16(sb + 2 * A_SZ * 2 + sBoj[0],          pBh0 + kt__);           \
            cp16(sb + (2 * A_SZ + B_SZ) * 2 + sBoj[0], pBl0 + kt__);           \
            cp16(sb + 2 * A_SZ * 2 + sBoj[1],          pBh1 + kt__);           \
            cp16(sb + (2 * A_SZ + B_SZ) * 2 + sBoj[1], pBl1 + kt__);           \
            cp16(sb + 2 * A_SZ * 2 + sBoj[2],          pBh2 + kt__);           \
            cp16(sb + (2 * A_SZ + B_SZ) * 2 + sBoj[2], pBl2 + kt__);           \
        }                                                                      \
        cp_commit();                                                           \
    } while (0)

    ISSUE(0);
    ISSUE(1);

    for (int t = 0; t < T; t++) {
        cp_wait1();
        __syncthreads();

        const uint32_t aH = smem_b + (uint32_t)((t & 1) * STG) * 2;
        const uint32_t aL = aH + A_SZ * 2;
        const uint32_t bH = aH + 2 * A_SZ * 2;
        const uint32_t bL = bH + B_SZ * 2;

#pragma unroll
        for (int h = 0; h < BK; h += 16) {
            uint32_t Af[2][4], Lf[2][4], Bf[6][2], Mf[6][2];

            // ---- stream 1: A_hi, B_hi loads, then hi*hi mmas ----
#pragma unroll
            for (int mi = 0; mi < 2; mi++) {
                const uint32_t d = offA + (uint32_t)((mi * 16 * SSTR + h) * 2);
                ldmx4(Af[mi][0], Af[mi][1], Af[mi][2], Af[mi][3], aH + d);
            }
#pragma unroll
            for (int np = 0; np < 3; np++) {
                const uint32_t d = offB + (uint32_t)((np * 16 * SSTR + h) * 2);
                ldmx4(Bf[2*np][0], Bf[2*np][1], Bf[2*np+1][0], Bf[2*np+1][1], bH + d);
            }
#pragma unroll
            for (int mi = 0; mi < 2; mi++)
#pragma unroll
                for (int ni = 0; ni < 6; ni++)
                    mma_bf16(acc[mi][ni][0], acc[mi][ni][1], acc[mi][ni][2], acc[mi][ni][3],
                             Af[mi][0], Af[mi][1], Af[mi][2], Af[mi][3],
                             Bf[ni][0], Bf[ni][1]);

            // ---- stream 2: B_lo loads overlap, then hi*lo mmas ----
#pragma unroll
            for (int np = 0; np < 3; np++) {
                const uint32_t d = offB + (uint32_t)((np * 16 * SSTR + h) * 2);
                ldmx4(Mf[2*np][0], Mf[2*np][1], Mf[2*np+1][0], Mf[2*np+1][1], bL + d);
            }
#pragma unroll
            for (int mi = 0; mi < 2; mi++)
#pragma unroll
                for (int ni = 0; ni < 6; ni++)
                    mma_bf16(acc[mi][ni][0], acc[mi][ni][1], acc[mi][ni][2], acc[mi][ni][3],
                             Af[mi][0], Af[mi][1], Af[mi][2], Af[mi][3],
                             Mf[ni][0], Mf[ni][1]);

            // ---- stream 3: A_lo loads overlap, then lo*hi mmas ----
#pragma unroll
            for (int mi = 0; mi < 2; mi++) {
                const uint32_t d = offA + (uint32_t)((mi * 16 * SSTR + h) * 2);
                ldmx4(Lf[mi][0], Lf[mi][1], Lf[mi][2], Lf[mi][3], aL + d);
            }
#pragma unroll
            for (int mi = 0; mi < 2; mi++)
#pragma unroll
                for (int ni = 0; ni < 6; ni++)
                    mma_bf16(acc[mi][ni][0], acc[mi][ni][1], acc[mi][ni][2], acc[mi][ni][3],
                             Lf[mi][0], Lf[mi][1], Lf[mi][2], Lf[mi][3],
                             Bf[ni][0], Bf[ni][1]);
        }

        __syncthreads();      // all warps done reading stage t
        ISSUE(t + 2);         // safe to overwrite buffer (t & 1)
    }
#undef ISSUE

    // ---- epilogue: stage acc in smem, then coalesced NCHW writes ----
    __syncthreads();
    float* sOut = reinterpret_cast<float*>(smem);   // [co][129] padded, 99072 B
#pragma unroll
    for (int mi = 0; mi < 2; mi++) {
#pragma unroll
        for (int half = 0; half < 2; half++) {
            int ml = wm * 32 + mi * 16 + grp + 8 * half;
#pragma unroll
            for (int ni = 0; ni < 6; ni++) {
                int cl = wn * 48 + ni * 8 + 2 * tg;
                sOut[cl * 129 + ml]       = acc[mi][ni][2 * half];
                sOut[(cl + 1) * 129 + ml] = acc[mi][ni][2 * half + 1];
            }
        }
    }
    __syncthreads();
    for (int idx = tid; idx < BN * BM; idx += 512) {
        int cl = idx >> 7;            // 0..191
        int ml = idx & 127;           // consecutive m for consecutive tid
        int m  = m0 + ml;
        int nimg2 = m / PIX;
        int pix2  = m - nimg2 * PIX;
        int co = co0 + cl;
        out[((size_t)nimg2 * NCO + co) * PIX + pix2] = sOut[cl * 129 + ml] + __ldg(&bias[co]);
    }
}

// ---------------------------------------------------------------------------
// GroupNorm + affine + ReLU (in-place fp32 NCHW) + NHWC hi/lo repack.
// ---------------------------------------------------------------------------
__global__ void __launch_bounds__(256) gn_relu_pack_kernel(
    float* __restrict__ buf, const float* __restrict__ sc, const float* __restrict__ bi,
    unsigned short* __restrict__ ph, unsigned short* __restrict__ pl)
{
    const int blk = blockIdx.x;
    const int n   = blk / NGROUP;
    const int g   = blk - n * NGROUP;
    float* base = buf + (size_t)blk * GSZ;
    const int tid = threadIdx.x;

    __shared__ float s_vals[GSZ];
    __shared__ float r1[8], r2[8];
    __shared__ float s_mu, s_inv;

    float vals[4];
    int cnt = 0;
    float s1 = 0.f, s2 = 0.f;
    for (int e = tid; e < GSZ; e += 256) {
        float x = base[e];
        vals[cnt++] = x;
        s1 += x; s2 += x * x;
    }
#pragma unroll
    for (int o = 16; o > 0; o >>= 1) {
        s1 += __shfl_xor_sync(0xffffffff, s1, o);
        s2 += __shfl_xor_sync(0xffffffff, s2, o);
    }
    const int w = tid >> 5, lane = tid & 31;
    if (lane == 0) { r1[w] = s1; r2[w] = s2; }
    __syncthreads();
    if (tid == 0) {
        float a = 0.f, b = 0.f;
#pragma unroll
        for (int i = 0; i < 8; i++) { a += r1[i]; b += r2[i]; }
        float mu  = a * (1.f / GSZ);
        float var = b * (1.f / GSZ) - mu * mu;
        s_mu = mu;
        s_inv = rsqrtf(var + 1e-5f);
    }
    __syncthreads();
    const float mu = s_mu, inv = s_inv;
    cnt = 0;
    for (int e = tid; e < GSZ; e += 256) {
        const int chl = e / PIX;
        const int ch  = g * 16 + chl;
        float y = (vals[cnt++] - mu) * inv * sc[ch] + bi[ch];
        y = fmaxf(y, 0.f);
        base[e] = y;
        s_vals[e] = y;
    }
    __syncthreads();

    if (tid < PIX) {
        const int py = tid / OHW, px = tid - py * OHW;
        uint32_t hw[8], lw[8];
#pragma unroll
        for (int j = 0; j < 8; j++) {
            unsigned short h0, l0, h1, l1;
            split_bf(s_vals[(2 * j) * PIX + tid], h0, l0);
            split_bf(s_vals[(2 * j + 1) * PIX + tid], h1, l1);
            hw[j] = (uint32_t)h0 | ((uint32_t)h1 << 16);
            lw[j] = (uint32_t)l0 | ((uint32_t)l1 << 16);
        }
        size_t o = ((size_t)(n * 81) + (py + 1) * 9 + (px + 1)) * NCO + g * 16;
        *(uint4*)(ph + o)     = make_uint4(hw[0], hw[1], hw[2], hw[3]);
        *(uint4*)(ph + o + 8) = make_uint4(hw[4], hw[5], hw[6], hw[7]);
        *(uint4*)(pl + o)     = make_uint4(lw[0], lw[1], lw[2], lw[3]);
        *(uint4*)(pl + o + 8) = make_uint4(lw[4], lw[5], lw[6], lw[7]);
    }
}

// ---------------------------------------------------------------------------
// Message passing, dst-major (unchanged).
// ---------------------------------------------------------------------------
__global__ void __launch_bounds__(256) msg_pass_kernel(
    const float* __restrict__ src_feat, const float* __restrict__ pts,
    const float* __restrict__ dw_w, const float* __restrict__ dw_b,
    const float* __restrict__ pw_w, const float* __restrict__ pw_b,
    float* __restrict__ outp)
{
    const int n = blockIdx.x;
    const int p = blockIdx.y;
    const int tid = threadIdx.x;

    __shared__ float s_in[NC * PIX];
    __shared__ float s_dw[NC * PIX];
    __shared__ float s_pw[NC * NC];

    float racc[13];
    const float* ptsb = pts + (size_t)(n * NCO + p * NC) * PIX;
#pragma unroll
    for (int k = 0; k < 13; k++) {
        int i = tid + k * 256;
        if (i < NC * PIX) racc[k] = ptsb[i];
    }

    const int e0 = c_estart[p], e1 = c_estart[p + 1];
    for (int ed = e0; ed < e1; ed++) {
        const int q = c_esrc[ed];
        const float* sb = src_feat + (size_t)(n * NCO + q * NC) * PIX;
        for (int i = tid; i < NC * PIX; i += 256) s_in[i] = sb[i];
        for (int i = tid; i < NC * NC; i += 256) s_pw[i] = pw_w[ed * NC * NC + i];
        __syncthreads();

        for (int i = tid; i < NC * PIX; i += 256) {
            const int c = i / PIX;
            const int pix = i - c * PIX;
            const int y = pix / OHW, x = pix - y * OHW;
            const float* wv = dw_w + (ed * NC + c) * 25;
            float a = dw_b[ed * NC + c];
#pragma unroll
            for (int dy = 0; dy < 5; dy++) {
                const int yy = y + dy - 2;
                if ((unsigned)yy < (unsigned)OHW) {
#pragma unroll
                    for (int dx = 0; dx < 5; dx++) {
                        const int xx = x + dx - 2;
                        if ((unsigned)xx < (unsigned)OHW)
                            a += wv[dy * 5 + dx] * s_in[c * PIX + yy * OHW + xx];
                    }
                }
            }
            s_dw[i] = a;
        }
        __syncthreads();

#pragma unroll
        for (int k = 0; k < 13; k++) {
            const int i = tid + k * 256;
            if (i < NC * PIX) {
                const int o = i / PIX;
                const int pix = i - o * PIX;
                float a = pw_b[ed * NC + o];
                const float* wr = &s_pw[o * NC];
#pragma unroll 8
                for (int ic = 0; ic < NC; ic++) a += wr[ic] * s_dw[ic * PIX + pix];
                racc[k] += a;
            }
        }
        __syncthreads();
    }

    float* ob = outp + (size_t)(n * NCO + p * NC) * PIX;
#pragma unroll
    for (int k = 0; k < 13; k++) {
        int i = tid + k * 256;
        if (i < NC * PIX) ob[i] = racc[k];
    }
}

__global__ void __launch_bounds__(256) copy_kernel(
    const float* __restrict__ s, float* __restrict__ d)
{
    int i = blockIdx.x * 256 + threadIdx.x;
    d[i] = s[i];
}

// ---------------------------------------------------------------------------
extern "C" void kernel_launch(void* const* d_in, const int* in_sizes, int n_in,
                              void* d_out, int out_size)
{
    const float* x       = (const float*)d_in[0];
    const float* conv0_w = (const float*)d_in[1];
    const float* conv0_b = (const float*)d_in[2];
    const float* gn0_s   = (const float*)d_in[3];
    const float* gn0_b   = (const float*)d_in[4];
    const float* convs_w = (const float*)d_in[5];
    const float* convs_b = (const float*)d_in[6];
    const float* gns_s   = (const float*)d_in[7];
    const float* gns_b   = (const float*)d_in[8];
    const float* fo_dw_w = (const float*)d_in[9];
    const float* fo_dw_b = (const float*)d_in[10];
    const float* fo_pw_w = (const float*)d_in[11];
    const float* fo_pw_b = (const float*)d_in[12];
    const float* so_dw_w = (const float*)d_in[13];
    const float* so_dw_b = (const float*)d_in[14];
    const float* so_pw_w = (const float*)d_in[15];
    const float* so_pw_b = (const float*)d_in[16];
    float* out = (float*)d_out;

    float *pA, *pB;
    unsigned short *pActH, *pActL, *pX0H, *pX0L, *pW0H, *pW0L, *pWrH, *pWrL;
    cudaGetSymbolAddress((void**)&pA,    g_bufA);
    cudaGetSymbolAddress((void**)&pB,    g_bufB);
    cudaGetSymbolAddress((void**)&pActH, g_acth);
    cudaGetSymbolAddress((void**)&pActL, g_actl);
    cudaGetSymbolAddress((void**)&pX0H,  g_x0h);
    cudaGetSymbolAddress((void**)&pX0L,  g_x0l);
    cudaGetSymbolAddress((void**)&pW0H,  g_w0h);
    cudaGetSymbolAddress((void**)&pW0L,  g_w0l);
    cudaGetSymbolAddress((void**)&pWrH,  g_wrh);
    cudaGetSymbolAddress((void**)&pWrL,  g_wrl);

    const int SMEM_CONV = 2 * (2 * BM * SSTR + 2 * BN * SSTR) * 2;   // 184320 B
    cudaFuncSetAttribute((const void*)conv_gemm_kernel<CIN0, 16, 2, KG0>,
                         cudaFuncAttributeMaxDynamicSharedMemorySize, SMEM_CONV);
    cudaFuncSetAttribute((const void*)conv_gemm_kernel<NCO, 9, 1, KGR>,
                         cudaFuncAttributeMaxDynamicSharedMemorySize, SMEM_CONV);

    // 1) pack inputs & weights (NHWC / tap-major)
    pack_x0_kernel<<<dim3(NROI, CIN0 / 32), 256>>>(x);
    pack_w0_kernel<<<(NCO * KG0) / 256, 256>>>(conv0_w);
    pack_wr_kernel<<<(NREST * NCO * KGR) / 256, 256>>>(convs_w);

    dim3 cgrid(NCO / BN, MTOT / BM);   // (3, 196): co fastest -> A L2 reuse

    // 2) conv0 (stride 2) + GN0/ReLU(+repack)
    conv_gemm_kernel<CIN0, 16, 2, KG0><<<cgrid, 512, SMEM_CONV>>>(
        pX0H, pX0L, pW0H, pW0L, conv0_b, pA);
    gn_relu_pack_kernel<<<NROI * NGROUP, 256>>>(pA, gn0_s, gn0_b, pActH, pActL);

    // 3) 7x [conv + GN/ReLU(+repack)], ping-pong
    float* cur = pA;
    float* nxt = pB;
    for (int l = 0; l < NREST; l++) {
        conv_gemm_kernel<NCO, 9, 1, KGR><<<cgrid, 512, SMEM_CONV>>>(
            pActH, pActL, pWrH + (size_t)l * NCO * KGR, pWrL + (size_t)l * NCO * KGR,
            convs_b + l * NCO, nxt);
        gn_relu_pack_kernel<<<NROI * NGROUP, 256>>>(nxt, gns_s + l * NCO, gns_b + l * NCO,
                                                    pActH, pActL);
        float* t = cur; cur = nxt; nxt = t;
    }
    // cur == final h, nxt free

    // 4) output half 1: h
    copy_kernel<<<HALF_OUT / 256, 256>>>(cur, out);

    // 5) first-order fusion -> nxt
    dim3 mgrid(NROI, NP);
    msg_pass_kernel<<<mgrid, 256>>>(cur, cur, fo_dw_w, fo_dw_b, fo_pw_w, fo_pw_b, nxt);

    // 6) second-order fusion -> output half 2
    msg_pass_kernel<<<mgrid, 256>>>(nxt, cur, so_dw_w, so_dw_b, so_pw_w, so_pw_b,
                                    out + HALF_OUT);
}

// round 14
// speedup vs baseline: 1.0620x; 1.0024x over previous
#include <cuda_runtime.h>
#include <cuda_bf16.h>
#include <cstdint>

// ---------------------------------------------------------------------------
// roi_grid_head, round 13: R13 GEMM core (BM128xBN192, BK=64, 2-stage,
// 512 thr, 4m x 4n, hi/lo 3-stream mma.sync) + tail fixes:
//   - last-layer GN writes `out` directly (copy_kernel removed)
//   - coalesced weight packing (kills 8x sector amplification)
//   - B-pointer register slimming in the GEMM loader
// ---------------------------------------------------------------------------

#define NROI   512
#define CIN0   256
#define OHW    7
#define PIX    49
#define NCO    576
#define NP     9
#define NC     64
#define NREST  7
#define KG0    (CIN0 * 9)            // 2304
#define KGR    (NCO * 9)             // 5184
#define MTOT   (NROI * PIX)          // 25088 = 196*128
#define NGROUP 36
#define GSZ    784
#define HALF_OUT (NROI * NCO * PIX)  // 14450688

#define BM 128
#define BN 192
#define BK 64
#define SSTR 72                       // smem row stride in bf16 units (144B)

// __device__ scratch (zero-initialized; padded border pixels never written)
__device__ unsigned short g_acth[NROI * 81 * NCO];    // [n][9x9 pad][576]
__device__ unsigned short g_actl[NROI * 81 * NCO];
__device__ unsigned short g_x0h[NROI * 256 * CIN0];   // [n][16x16 pad][256]
__device__ unsigned short g_x0l[NROI * 256 * CIN0];
__device__ unsigned short g_w0h[NCO * KG0];           // [co][tap*256+ci]
__device__ unsigned short g_w0l[NCO * KG0];
__device__ unsigned short g_wrh[NREST * NCO * KGR];   // [l][co][tap*576+ci]
__device__ unsigned short g_wrl[NREST * NCO * KGR];
__device__ float g_bufA[HALF_OUT];
__device__ float g_bufB[HALF_OUT];

__constant__ int c_esrc[24]   = {1,3, 0,2,4, 1,5, 0,4,6, 1,3,5,7, 2,4,8, 3,7, 4,6,8, 5,7};
__constant__ int c_estart[10] = {0,2,5,7,10,14,17,19,22,24};

// ---------------------------------------------------------------------------
__device__ __forceinline__ void split_bf(float f, unsigned short& h, unsigned short& l) {
    __nv_bfloat16 bh = __float2bfloat16(f);
    float r = f - __bfloat162float(bh);
    h = __bfloat16_as_ushort(bh);
    l = __bfloat16_as_ushort(__float2bfloat16(r));
}

__device__ __forceinline__ void mma_bf16(float& c0, float& c1, float& c2, float& c3,
                                         uint32_t a0, uint32_t a1, uint32_t a2, uint32_t a3,
                                         uint32_t b0, uint32_t b1) {
    asm volatile(
        "mma.sync.aligned.m16n8k16.row.col.f32.bf16.bf16.f32 "
        "{%0,%1,%2,%3},{%4,%5,%6,%7},{%8,%9},{%0,%1,%2,%3};\n"
        : "+f"(c0), "+f"(c1), "+f"(c2), "+f"(c3)
        : "r"(a0), "r"(a1), "r"(a2), "r"(a3), "r"(b0), "r"(b1));
}

__device__ __forceinline__ void ldmx4(uint32_t& r0, uint32_t& r1, uint32_t& r2, uint32_t& r3,
                                      uint32_t addr) {
    asm volatile("ldmatrix.sync.aligned.m8n8.x4.shared.b16 {%0,%1,%2,%3},[%4];\n"
                 : "=r"(r0), "=r"(r1), "=r"(r2), "=r"(r3) : "r"(addr));
}

__device__ __forceinline__ void cp16(uint32_t daddr, const void* src) {
    asm volatile("cp.async.cg.shared.global [%0], [%1], 16;\n" :: "r"(daddr), "l"(src));
}
__device__ __forceinline__ void cp_commit() { asm volatile("cp.async.commit_group;\n" ::: "memory"); }
__device__ __forceinline__ void cp_wait1()  { asm volatile("cp.async.wait_group 1;\n" ::: "memory"); }

// ---------------------------------------------------------------------------
// Packing kernels
// ---------------------------------------------------------------------------
__global__ void __launch_bounds__(256) pack_x0_kernel(const float* __restrict__ x) {
    __shared__ float sx[32 * 196];
    const int n  = blockIdx.x;
    const int c0 = blockIdx.y * 32;
    const int tid = threadIdx.x;
    for (int idx = tid; idx < 32 * 196; idx += 256) {
        int c = idx / 196, pix = idx - c * 196;
        sx[idx] = x[((size_t)(n * CIN0 + c0 + c)) * 196 + pix];
    }
    __syncthreads();
    for (int idx = tid; idx < 196 * 32; idx += 256) {
        int pix = idx >> 5, cl = idx & 31;
        int y = pix / 14, xx = pix - y * 14;
        unsigned short h, l;
        split_bf(sx[cl * 196 + pix], h, l);
        size_t o = ((size_t)(n * 256) + (y + 1) * 16 + (xx + 1)) * CIN0 + c0 + cl;
        g_x0h[o] = h; g_x0l[o] = l;
    }
}

// conv0 weights: thread = (co, ci); reads 9 consecutive floats, writes per-tap
// coalesced (ci consecutive across threads).
__global__ void __launch_bounds__(256) pack_w0_kernel(const float* __restrict__ w) {
    int i = blockIdx.x * 256 + threadIdx.x;       // NCO*CIN0
    int co = i / CIN0, ci = i - co * CIN0;
    const float* wp = w + ((size_t)(co * CIN0 + ci)) * 9;
    size_t ob = (size_t)co * KG0 + ci;
#pragma unroll
    for (int tap = 0; tap < 9; tap++) {
        unsigned short h, l;
        split_bf(wp[tap], h, l);
        g_w0h[ob + (size_t)tap * CIN0] = h;
        g_w0l[ob + (size_t)tap * CIN0] = l;
    }
}

// conv weights: thread = (l, co, ci); same coalescing scheme.
__global__ void __launch_bounds__(256) pack_wr_kernel(const float* __restrict__ w) {
    int i = blockIdx.x * 256 + threadIdx.x;       // NREST*NCO*NCO
    int l = i / (NCO * NCO);
    int r = i - l * (NCO * NCO);
    int co = r / NCO, ci = r - co * NCO;
    const float* wp = w + ((size_t)(l * NCO + co) * NCO + ci) * 9;
    size_t ob = (size_t)(l * NCO + co) * KGR + ci;
#pragma unroll
    for (int tap = 0; tap < 9; tap++) {
        unsigned short h, lo;
        split_bf(wp[tap], h, lo);
        g_wrh[ob + (size_t)tap * NCO] = h;
        g_wrl[ob + (size_t)tap * NCO] = lo;
    }
}

// ---------------------------------------------------------------------------
// NHWC implicit-GEMM conv: out[m][co] = sum_k A[m][k]*B[co][k],
// k = tap*CPT + ci, A gathered from padded NHWC planes.
// BM=128 BN=192 BK=64, 512 threads (16 warps, 4m x 4n, warp tile 32x48),
// 2-stage cp.async double buffer, hi/lo 3-stream mma, staged epilogue.
// ---------------------------------------------------------------------------
template<int CPT, int PITCH, int S, int K>
__global__ void __launch_bounds__(512, 1) conv_gemm_kernel(
    const unsigned short* __restrict__ Ah, const unsigned short* __restrict__ Al,
    const unsigned short* __restrict__ Bgh, const unsigned short* __restrict__ Bgl,
    const float* __restrict__ bias, float* __restrict__ out)
{
    extern __shared__ unsigned short smem[];
    constexpr int A_SZ  = BM * SSTR;              // 9216 u16
    constexpr int B_SZ  = BN * SSTR;              // 13824 u16
    constexpr int STG   = 2 * A_SZ + 2 * B_SZ;    // 46080 u16 = 92160 B
    constexpr int T     = K / BK;
    constexpr int CPT64 = CPT / BK;
    constexpr int NPIXP = PITCH * PITCH;

    const int tid  = threadIdx.x;
    const int lane = tid & 31;
    const int warp = tid >> 5;
    const int wm = warp >> 2, wn = warp & 3;      // 4 x 4 warp grid
    const int grp = lane >> 2, tg = lane & 3;
    const int co0 = blockIdx.x * BN;
    const int m0  = blockIdx.y * BM;

    const uint32_t smem_b = (uint32_t)__cvta_generic_to_shared(smem);

    // A loader: 128 rows x 8 chunks(16B); thread covers 2 consecutive chunks.
    const int ar  = tid >> 2;                     // 0..127
    const int ach = (tid & 3) * 16;               // u16 offset {0,16,32,48}
    const int am   = m0 + ar;
    const int nimg = am / PIX;
    const int apix = am - nimg * PIX;
    const int ay   = apix / OHW, ax = apix - ay * OHW;
    const unsigned short* rowH = Ah + ((size_t)nimg * NPIXP
                                       + (size_t)(S * ay) * PITCH + (S * ax)) * CPT;
    const unsigned short* rowL = Al + ((size_t)nimg * NPIXP
                                       + (size_t)(S * ay) * PITCH + (S * ax)) * CPT;
    const uint32_t sAo = (uint32_t)((ar * SSTR + ach) * 2);

    // B loader: 192 rows x 8 chunks = 1536 slots; slots tid, tid+512, tid+1024.
    // Single base pointer + int offsets (register slimming).
    const unsigned short* BgH0 = Bgh + (size_t)co0 * K;
    const unsigned short* BgL0 = Bgl + (size_t)co0 * K;
    int boff[3];
    uint32_t sBoj[3];
#pragma unroll
    for (int j = 0; j < 3; j++) {
        int slot = tid + j * 512;
        int br = slot >> 3;                       // 0..191
        int bc = (slot & 7) * 8;                  // u16 offset
        boff[j] = br * K + bc;
        sBoj[j] = (uint32_t)((br * SSTR + bc) * 2);
    }

    // ldmatrix per-thread byte offsets within plane
    const uint32_t offA = (uint32_t)(((wm * 32 + (lane & 15)) * SSTR + 8 * (lane >> 4)) * 2);
    const uint32_t offB = (uint32_t)(((wn * 48 + (lane & 7) + 8 * (lane >> 4)) * SSTR
                                      + 8 * ((lane >> 3) & 1)) * 2);

    float acc[2][6][4];
#pragma unroll
    for (int a = 0; a < 2; a++)
#pragma unroll
        for (int b = 0; b < 6; b++)
#pragma unroll
            for (int c = 0; c < 4; c++) acc[a][b][c] = 0.f;

#define ISSUE(t_)                                                              \
    do {                                                                       \
        int t__ = (t_);                                                        \
        if (t__ < T) {                                                         \
            const uint32_t sb = smem_b + (uint32_t)((t__ & 1) * STG) * 2;      \
            const int tap__ = t__ / CPT64;                                     \
            const int rem__ = t__ - tap__ * CPT64;                             \
            const int ky__  = tap__ / 3;                                       \
            const int kx__  = tap__ - ky__ * 3;                                \
            const int poff__ = (ky__ * PITCH + kx__) * CPT + rem__ * BK + ach; \
            cp16(sb + sAo,                rowH + poff__);                      \
            cp16(sb + sAo + 16,           rowH + poff__ + 8);                  \
            cp16(sb + A_SZ * 2 + sAo,      rowL + poff__);                     \
            cp16(sb + A_SZ * 2 + sAo + 16, rowL + poff__ + 8);                 \
            const int kt__ = t__ * BK;                                         \
            _Pragma("unroll")                                                  \
            for (int j = 0; j < 3; j++) {                                      \
                cp16(sb + 2 * A_SZ * 2 + sBoj[j],          BgH0 + boff[j] + kt__); \
                cp16(sb + (2 * A_SZ + B_SZ) * 2 + sBoj[j], BgL0 + boff[j] + kt__); \
            }                                                                  \
        }                                                                      \
        cp_commit();                                                           \
    } while (0)

    ISSUE(0);
    ISSUE(1);

    for (int t = 0; t < T; t++) {
        cp_wait1();
        __syncthreads();

        const uint32_t aH = smem_b + (uint32_t)((t & 1) * STG) * 2;
        const uint32_t aL = aH + A_SZ * 2;
        const uint32_t bH = aH + 2 * A_SZ * 2;
        const uint32_t bL = bH + B_SZ * 2;

#pragma unroll
        for (int h = 0; h < BK; h += 16) {
            uint32_t Af[2][4], Lf[2][4], Bf[6][2], Mf[6][2];

            // ---- stream 1: A_hi, B_hi loads, then hi*hi mmas ----
#pragma unroll
            for (int mi = 0; mi < 2; mi++) {
                const uint32_t d = offA + (uint32_t)((mi * 16 * SSTR + h) * 2);
                ldmx4(Af[mi][0], Af[mi][1], Af[mi][2], Af[mi][3], aH + d);
            }
#pragma unroll
            for (int np = 0; np < 3; np++) {
                const uint32_t d = offB + (uint32_t)((np * 16 * SSTR + h) * 2);
                ldmx4(Bf[2*np][0], Bf[2*np][1], Bf[2*np+1][0], Bf[2*np+1][1], bH + d);
            }
#pragma unroll
            for (int mi = 0; mi < 2; mi++)
#pragma unroll
                for (int ni = 0; ni < 6; ni++)
                    mma_bf16(acc[mi][ni][0], acc[mi][ni][1], acc[mi][ni][2], acc[mi][ni][3],
                             Af[mi][0], Af[mi][1], Af[mi][2], Af[mi][3],
                             Bf[ni][0], Bf[ni][1]);

            // ---- stream 2: B_lo loads overlap, then hi*lo mmas ----
#pragma unroll
            for (int np = 0; np < 3; np++) {
                const uint32_t d = offB + (uint32_t)((np * 16 * SSTR + h) * 2);
                ldmx4(Mf[2*np][0], Mf[2*np][1], Mf[2*np+1][0], Mf[2*np+1][1], bL + d);
            }
#pragma unroll
            for (int mi = 0; mi < 2; mi++)
#pragma unroll
                for (int ni = 0; ni < 6; ni++)
                    mma_bf16(acc[mi][ni][0], acc[mi][ni][1], acc[mi][ni][2], acc[mi][ni][3],
                             Af[mi][0], Af[mi][1], Af[mi][2], Af[mi][3],
                             Mf[ni][0], Mf[ni][1]);

            // ---- stream 3: A_lo loads overlap, then lo*hi mmas ----
#pragma unroll
            for (int mi = 0; mi < 2; mi++) {
                const uint32_t d = offA + (uint32_t)((mi * 16 * SSTR + h) * 2);
                ldmx4(Lf[mi][0], Lf[mi][1], Lf[mi][2], Lf[mi][3], aL + d);
            }
#pragma unroll
            for (int mi = 0; mi < 2; mi++)
#pragma unroll
                for (int ni = 0; ni < 6; ni++)
                    mma_bf16(acc[mi][ni][0], acc[mi][ni][1], acc[mi][ni][2], acc[mi][ni][3],
                             Lf[mi][0], Lf[mi][1], Lf[mi][2], Lf[mi][3],
                             Bf[ni][0], Bf[ni][1]);
        }

        __syncthreads();      // all warps done reading stage t
        ISSUE(t + 2);         // safe to overwrite buffer (t & 1)
    }
#undef ISSUE

    // ---- epilogue: stage acc in smem, then coalesced NCHW writes ----
    __syncthreads();
    float* sOut = reinterpret_cast<float*>(smem);   // [co][129] padded, 99072 B
#pragma unroll
    for (int mi = 0; mi < 2; mi++) {
#pragma unroll
        for (int half = 0; half < 2; half++) {
            int ml = wm * 32 + mi * 16 + grp + 8 * half;
#pragma unroll
            for (int ni = 0; ni < 6; ni++) {
                int cl = wn * 48 + ni * 8 + 2 * tg;
                sOut[cl * 129 + ml]       = acc[mi][ni][2 * half];
                sOut[(cl + 1) * 129 + ml] = acc[mi][ni][2 * half + 1];
            }
        }
    }
    __syncthreads();
    for (int idx = tid; idx < BN * BM; idx += 512) {
        int cl = idx >> 7;            // 0..191
        int ml = idx & 127;           // consecutive m for consecutive tid
        int m  = m0 + ml;
        int nimg2 = m / PIX;
        int pix2  = m - nimg2 * PIX;
        int co = co0 + cl;
        out[((size_t)nimg2 * NCO + co) * PIX + pix2] = sOut[cl * 129 + ml] + __ldg(&bias[co]);
    }
}

// ---------------------------------------------------------------------------
// GroupNorm + affine + ReLU (in-place fp32 NCHW) + NHWC hi/lo repack.
// Optionally mirrors the normalized output into `outc` (same layout) so the
// last layer writes the kernel output directly (no copy pass).
// ---------------------------------------------------------------------------
__global__ void __launch_bounds__(256) gn_relu_pack_kernel(
    float* __restrict__ buf, const float* __restrict__ sc, const float* __restrict__ bi,
    unsigned short* __restrict__ ph, unsigned short* __restrict__ pl,
    float* __restrict__ outc)
{
    const int blk = blockIdx.x;
    const int n   = blk / NGROUP;
    const int g   = blk - n * NGROUP;
    float* base = buf + (size_t)blk * GSZ;
    const int tid = threadIdx.x;

    __shared__ float s_vals[GSZ];
    __shared__ float r1[8], r2[8];
    __shared__ float s_mu, s_inv;

    float vals[4];
    int cnt = 0;
    float s1 = 0.f, s2 = 0.f;
    for (int e = tid; e < GSZ; e += 256) {
        float x = base[e];
        vals[cnt++] = x;
        s1 += x; s2 += x * x;
    }
#pragma unroll
    for (int o = 16; o > 0; o >>= 1) {
        s1 += __shfl_xor_sync(0xffffffff, s1, o);
        s2 += __shfl_xor_sync(0xffffffff, s2, o);
    }
    const int w = tid >> 5, lane = tid & 31;
    if (lane == 0) { r1[w] = s1; r2[w] = s2; }
    __syncthreads();
    if (tid == 0) {
        float a = 0.f, b = 0.f;
#pragma unroll
        for (int i = 0; i < 8; i++) { a += r1[i]; b += r2[i]; }
        float mu  = a * (1.f / GSZ);
        float var = b * (1.f / GSZ) - mu * mu;
        s_mu = mu;
        s_inv = rsqrtf(var + 1e-5f);
    }
    __syncthreads();
    const float mu = s_mu, inv = s_inv;
    cnt = 0;
    for (int e = tid; e < GSZ; e += 256) {
        const int chl = e / PIX;
        const int ch  = g * 16 + chl;
        float y = (vals[cnt++] - mu) * inv * sc[ch] + bi[ch];
        y = fmaxf(y, 0.f);
        base[e] = y;
        s_vals[e] = y;
        if (outc) outc[(size_t)blk * GSZ + e] = y;
    }
    __syncthreads();

    if (tid < PIX) {
        const int py = tid / OHW, px = tid - py * OHW;
        uint32_t hw[8], lw[8];
#pragma unroll
        for (int j = 0; j < 8; j++) {
            unsigned short h0, l0, h1, l1;
            split_bf(s_vals[(2 * j) * PIX + tid], h0, l0);
            split_bf(s_vals[(2 * j + 1) * PIX + tid], h1, l1);
            hw[j] = (uint32_t)h0 | ((uint32_t)h1 << 16);
            lw[j] = (uint32_t)l0 | ((uint32_t)l1 << 16);
        }
        size_t o = ((size_t)(n * 81) + (py + 1) * 9 + (px + 1)) * NCO + g * 16;
        *(uint4*)(ph + o)     = make_uint4(hw[0], hw[1], hw[2], hw[3]);
        *(uint4*)(ph + o + 8) = make_uint4(hw[4], hw[5], hw[6], hw[7]);
        *(uint4*)(pl + o)     = make_uint4(lw[0], lw[1], lw[2], lw[3]);
        *(uint4*)(pl + o + 8) = make_uint4(lw[4], lw[5], lw[6], lw[7]);
    }
}

// ---------------------------------------------------------------------------
// Message passing, dst-major (unchanged).
// ---------------------------------------------------------------------------
__global__ void __launch_bounds__(256) msg_pass_kernel(
    const float* __restrict__ src_feat, const float* __restrict__ pts,
    const float* __restrict__ dw_w, const float* __restrict__ dw_b,
    const float* __restrict__ pw_w, const float* __restrict__ pw_b,
    float* __restrict__ outp)
{
    const int n = blockIdx.x;
    const int p = blockIdx.y;
    const int tid = threadIdx.x;

    __shared__ float s_in[NC * PIX];
    __shared__ float s_dw[NC * PIX];
    __shared__ float s_pw[NC * NC];

    float racc[13];
    const float* ptsb = pts + (size_t)(n * NCO + p * NC) * PIX;
#pragma unroll
    for (int k = 0; k < 13; k++) {
        int i = tid + k * 256;
        if (i < NC * PIX) racc[k] = ptsb[i];
    }

    const int e0 = c_estart[p], e1 = c_estart[p + 1];
    for (int ed = e0; ed < e1; ed++) {
        const int q = c_esrc[ed];
        const float* sb = src_feat + (size_t)(n * NCO + q * NC) * PIX;
        for (int i = tid; i < NC * PIX; i += 256) s_in[i] = sb[i];
        for (int i = tid; i < NC * NC; i += 256) s_pw[i] = pw_w[ed * NC * NC + i];
        __syncthreads();

        for (int i = tid; i < NC * PIX; i += 256) {
            const int c = i / PIX;
            const int pix = i - c * PIX;
            const int y = pix / OHW, x = pix - y * OHW;
            const float* wv = dw_w + (ed * NC + c) * 25;
            float a = dw_b[ed * NC + c];
#pragma unroll
            for (int dy = 0; dy < 5; dy++) {
                const int yy = y + dy - 2;
                if ((unsigned)yy < (unsigned)OHW) {
#pragma unroll
                    for (int dx = 0; dx < 5; dx++) {
                        const int xx = x + dx - 2;
                        if ((unsigned)xx < (unsigned)OHW)
                            a += wv[dy * 5 + dx] * s_in[c * PIX + yy * OHW + xx];
                    }
                }
            }
            s_dw[i] = a;
        }
        __syncthreads();

#pragma unroll
        for (int k = 0; k < 13; k++) {
            const int i = tid + k * 256;
            if (i < NC * PIX) {
                const int o = i / PIX;
                const int pix = i - o * PIX;
                float a = pw_b[ed * NC + o];
                const float* wr = &s_pw[o * NC];
#pragma unroll 8
                for (int ic = 0; ic < NC; ic++) a += wr[ic] * s_dw[ic * PIX + pix];
                racc[k] += a;
            }
        }
        __syncthreads();
    }

    float* ob = outp + (size_t)(n * NCO + p * NC) * PIX;
#pragma unroll
    for (int k = 0; k < 13; k++) {
        int i = tid + k * 256;
        if (i < NC * PIX) ob[i] = racc[k];
    }
}

// ---------------------------------------------------------------------------
extern "C" void kernel_launch(void* const* d_in, const int* in_sizes, int n_in,
                              void* d_out, int out_size)
{
    const float* x       = (const float*)d_in[0];
    const float* conv0_w = (const float*)d_in[1];
    const float* conv0_b = (const float*)d_in[2];
    const float* gn0_s   = (const float*)d_in[3];
    const float* gn0_b   = (const float*)d_in[4];
    const float* convs_w = (const float*)d_in[5];
    const float* convs_b = (const float*)d_in[6];
    const float* gns_s   = (const float*)d_in[7];
    const float* gns_b   = (const float*)d_in[8];
    const float* fo_dw_w = (const float*)d_in[9];
    const float* fo_dw_b = (const float*)d_in[10];
    const float* fo_pw_w = (const float*)d_in[11];
    const float* fo_pw_b = (const float*)d_in[12];
    const float* so_dw_w = (const float*)d_in[13];
    const float* so_dw_b = (const float*)d_in[14];
    const float* so_pw_w = (const float*)d_in[15];
    const float* so_pw_b = (const float*)d_in[16];
    float* out = (float*)d_out;

    float *pA, *pB;
    unsigned short *pActH, *pActL, *pX0H, *pX0L, *pW0H, *pW0L, *pWrH, *pWrL;
    cudaGetSymbolAddress((void**)&pA,    g_bufA);
    cudaGetSymbolAddress((void**)&pB,    g_bufB);
    cudaGetSymbolAddress((void**)&pActH, g_acth);
    cudaGetSymbolAddress((void**)&pActL, g_actl);
    cudaGetSymbolAddress((void**)&pX0H,  g_x0h);
    cudaGetSymbolAddress((void**)&pX0L,  g_x0l);
    cudaGetSymbolAddress((void**)&pW0H,  g_w0h);
    cudaGetSymbolAddress((void**)&pW0L,  g_w0l);
    cudaGetSymbolAddress((void**)&pWrH,  g_wrh);
    cudaGetSymbolAddress((void**)&pWrL,  g_wrl);

    const int SMEM_CONV = 2 * (2 * BM * SSTR + 2 * BN * SSTR) * 2;   // 184320 B
    cudaFuncSetAttribute((const void*)conv_gemm_kernel<CIN0, 16, 2, KG0>,
                         cudaFuncAttributeMaxDynamicSharedMemorySize, SMEM_CONV);
    cudaFuncSetAttribute((const void*)conv_gemm_kernel<NCO, 9, 1, KGR>,
                         cudaFuncAttributeMaxDynamicSharedMemorySize, SMEM_CONV);

    // 1) pack inputs & weights (NHWC / tap-major), coalesced
    pack_x0_kernel<<<dim3(NROI, CIN0 / 32), 256>>>(x);
    pack_w0_kernel<<<(NCO * CIN0) / 256, 256>>>(conv0_w);
    pack_wr_kernel<<<(NREST * NCO * NCO) / 256, 256>>>(convs_w);

    dim3 cgrid(NCO / BN, MTOT / BM);   // (3, 196): co fastest -> A L2 reuse

    // 2) conv0 (stride 2) + GN0/ReLU(+repack)
    conv_gemm_kernel<CIN0, 16, 2, KG0><<<cgrid, 512, SMEM_CONV>>>(
        pX0H, pX0L, pW0H, pW0L, conv0_b, pA);
    gn_relu_pack_kernel<<<NROI * NGROUP, 256>>>(pA, gn0_s, gn0_b, pActH, pActL, nullptr);

    // 3) 7x [conv + GN/ReLU(+repack)], ping-pong; last GN also writes out
    float* cur = pA;
    float* nxt = pB;
    for (int l = 0; l < NREST; l++) {
        conv_gemm_kernel<NCO, 9, 1, KGR><<<cgrid, 512, SMEM_CONV>>>(
            pActH, pActL, pWrH + (size_t)l * NCO * KGR, pWrL + (size_t)l * NCO * KGR,
            convs_b + l * NCO, nxt);
        gn_relu_pack_kernel<<<NROI * NGROUP, 256>>>(
            nxt, gns_s + l * NCO, gns_b + l * NCO, pActH, pActL,
            (l == NREST - 1) ? out : nullptr);
        float* t = cur; cur = nxt; nxt = t;
    }
    // cur == final h (also already copied into out half 1), nxt free

    // 4) first-order fusion -> nxt
    dim3 mgrid(NROI, NP);
    msg_pass_kernel<<<mgrid, 256>>>(cur, cur, fo_dw_w, fo_dw_b, fo_pw_w, fo_pw_b, nxt);

    // 5) second-order fusion -> output half 2
    msg_pass_kernel<<<mgrid, 256>>>(nxt, cur, so_dw_w, so_dw_b, so_pw_w, so_pw_b,
                                    out + HALF_OUT);
}

// round 15
// speedup vs baseline: 1.3769x; 1.2966x over previous
#include <cuda_runtime.h>
#include <cuda_fp16.h>
#include <cstdint>

// ---------------------------------------------------------------------------
// roi_grid_head, round 14: fp16 2-stream split GEMM.
//   A = Ah + Al (fp16 split, exact to ~2^-22), B = fp16(B) (one plane).
//   D = Ah*B + Al*B  (fp32 accum)  -> 2 mmas per k16 instead of 3,
//   error only from B rounding (~1.4e-4/layer, ~4e-4 total, gate 1e-3).
// Core otherwise = R14: BM128xBN192, BK=64, 2-stage cp.async, 512 thr,
// 4m x 4n warps (32x48), staged coalesced epilogue, fused GN tail.
// ---------------------------------------------------------------------------

#define NROI   512
#define CIN0   256
#define OHW    7
#define PIX    49
#define NCO    576
#define NP     9
#define NC     64
#define NREST  7
#define KG0    (CIN0 * 9)            // 2304
#define KGR    (NCO * 9)             // 5184
#define MTOT   (NROI * PIX)          // 25088 = 196*128
#define NGROUP 36
#define GSZ    784
#define HALF_OUT (NROI * NCO * PIX)  // 14450688

#define BM 128
#define BN 192
#define BK 64
#define SSTR 72                       // smem row stride in fp16 units (144B)

// __device__ scratch (zero-initialized; padded border pixels never written)
__device__ unsigned short g_acth[NROI * 81 * NCO];    // act hi [n][9x9 pad][576]
__device__ unsigned short g_actl[NROI * 81 * NCO];    // act lo
__device__ unsigned short g_x0h[NROI * 256 * CIN0];   // x hi [n][16x16 pad][256]
__device__ unsigned short g_x0l[NROI * 256 * CIN0];
__device__ unsigned short g_w0h[NCO * KG0];           // conv0 W fp16 [co][tap*256+ci]
__device__ unsigned short g_wrh[NREST * NCO * KGR];   // convs W fp16
__device__ float g_bufA[HALF_OUT];
__device__ float g_bufB[HALF_OUT];

__constant__ int c_esrc[24]   = {1,3, 0,2,4, 1,5, 0,4,6, 1,3,5,7, 2,4,8, 3,7, 4,6,8, 5,7};
__constant__ int c_estart[10] = {0,2,5,7,10,14,17,19,22,24};

// ---------------------------------------------------------------------------
__device__ __forceinline__ void split_f16(float f, unsigned short& h, unsigned short& l) {
    __half hh = __float2half(f);
    float r = f - __half2float(hh);
    h = __half_as_ushort(hh);
    l = __half_as_ushort(__float2half(r));
}

__device__ __forceinline__ unsigned short to_f16(float f) {
    return __half_as_ushort(__float2half(f));
}

__device__ __forceinline__ void mma_f16(float& c0, float& c1, float& c2, float& c3,
                                        uint32_t a0, uint32_t a1, uint32_t a2, uint32_t a3,
                                        uint32_t b0, uint32_t b1) {
    asm volatile(
        "mma.sync.aligned.m16n8k16.row.col.f32.f16.f16.f32 "
        "{%0,%1,%2,%3},{%4,%5,%6,%7},{%8,%9},{%0,%1,%2,%3};\n"
        : "+f"(c0), "+f"(c1), "+f"(c2), "+f"(c3)
        : "r"(a0), "r"(a1), "r"(a2), "r"(a3), "r"(b0), "r"(b1));
}

__device__ __forceinline__ void ldmx4(uint32_t& r0, uint32_t& r1, uint32_t& r2, uint32_t& r3,
                                      uint32_t addr) {
    asm volatile("ldmatrix.sync.aligned.m8n8.x4.shared.b16 {%0,%1,%2,%3},[%4];\n"
                 : "=r"(r0), "=r"(r1), "=r"(r2), "=r"(r3) : "r"(addr));
}

__device__ __forceinline__ void cp16(uint32_t daddr, const void* src) {
    asm volatile("cp.async.cg.shared.global [%0], [%1], 16;\n" :: "r"(daddr), "l"(src));
}
__device__ __forceinline__ void cp_commit() { asm volatile("cp.async.commit_group;\n" ::: "memory"); }
__device__ __forceinline__ void cp_wait1()  { asm volatile("cp.async.wait_group 1;\n" ::: "memory"); }

// ---------------------------------------------------------------------------
// Packing kernels
// ---------------------------------------------------------------------------
__global__ void __launch_bounds__(256) pack_x0_kernel(const float* __restrict__ x) {
    __shared__ float sx[32 * 196];
    const int n  = blockIdx.x;
    const int c0 = blockIdx.y * 32;
    const int tid = threadIdx.x;
    for (int idx = tid; idx < 32 * 196; idx += 256) {
        int c = idx / 196, pix = idx - c * 196;
        sx[idx] = x[((size_t)(n * CIN0 + c0 + c)) * 196 + pix];
    }
    __syncthreads();
    for (int idx = tid; idx < 196 * 32; idx += 256) {
        int pix = idx >> 5, cl = idx & 31;
        int y = pix / 14, xx = pix - y * 14;
        unsigned short h, l;
        split_f16(sx[cl * 196 + pix], h, l);
        size_t o = ((size_t)(n * 256) + (y + 1) * 16 + (xx + 1)) * CIN0 + c0 + cl;
        g_x0h[o] = h; g_x0l[o] = l;
    }
}

// conv0 weights: thread = (co, ci); reads 9 consecutive floats, writes per-tap.
__global__ void __launch_bounds__(256) pack_w0_kernel(const float* __restrict__ w) {
    int i = blockIdx.x * 256 + threadIdx.x;       // NCO*CIN0
    int co = i / CIN0, ci = i - co * CIN0;
    const float* wp = w + ((size_t)(co * CIN0 + ci)) * 9;
    size_t ob = (size_t)co * KG0 + ci;
#pragma unroll
    for (int tap = 0; tap < 9; tap++)
        g_w0h[ob + (size_t)tap * CIN0] = to_f16(wp[tap]);
}

__global__ void __launch_bounds__(256) pack_wr_kernel(const float* __restrict__ w) {
    int i = blockIdx.x * 256 + threadIdx.x;       // NREST*NCO*NCO
    int l = i / (NCO * NCO);
    int r = i - l * (NCO * NCO);
    int co = r / NCO, ci = r - co * NCO;
    const float* wp = w + ((size_t)(l * NCO + co) * NCO + ci) * 9;
    size_t ob = (size_t)(l * NCO + co) * KGR + ci;
#pragma unroll
    for (int tap = 0; tap < 9; tap++)
        g_wrh[ob + (size_t)tap * NCO] = to_f16(wp[tap]);
}

// ---------------------------------------------------------------------------
// NHWC implicit-GEMM conv: out[m][co] = sum_k A[m][k]*B[co][k],
// k = tap*CPT + ci, A gathered from padded NHWC fp16 hi/lo planes,
// B single fp16 plane. BM=128 BN=192 BK=64, 512 threads (16 warps, 4m x 4n,
// warp tile 32x48), 2-stage cp.async, 2-stream mma, staged epilogue.
// ---------------------------------------------------------------------------
template<int CPT, int PITCH, int S, int K>
__global__ void __launch_bounds__(512, 1) conv_gemm_kernel(
    const unsigned short* __restrict__ Ah, const unsigned short* __restrict__ Al,
    const unsigned short* __restrict__ Bg,
    const float* __restrict__ bias, float* __restrict__ out)
{
    extern __shared__ unsigned short smem[];
    constexpr int A_SZ  = BM * SSTR;              // 9216 u16
    constexpr int B_SZ  = BN * SSTR;              // 13824 u16
    constexpr int STG   = 2 * A_SZ + B_SZ;        // 32256 u16 = 64512 B
    constexpr int T     = K / BK;
    constexpr int CPT64 = CPT / BK;
    constexpr int NPIXP = PITCH * PITCH;

    const int tid  = threadIdx.x;
    const int lane = tid & 31;
    const int warp = tid >> 5;
    const int wm = warp >> 2, wn = warp & 3;      // 4 x 4 warp grid
    const int grp = lane >> 2, tg = lane & 3;
    const int co0 = blockIdx.x * BN;
    const int m0  = blockIdx.y * BM;

    const uint32_t smem_b = (uint32_t)__cvta_generic_to_shared(smem);

    // A loader: 128 rows x 4 chunks(32 u16 covered as 2 cp16); slot = tid.
    const int ar  = tid >> 2;                     // 0..127
    const int ach = (tid & 3) * 16;               // u16 offset {0,16,32,48}
    const int am   = m0 + ar;
    const int nimg = am / PIX;
    const int apix = am - nimg * PIX;
    const int ay   = apix / OHW, ax = apix - ay * OHW;
    const unsigned short* rowH = Ah + ((size_t)nimg * NPIXP
                                       + (size_t)(S * ay) * PITCH + (S * ax)) * CPT;
    const unsigned short* rowL = Al + ((size_t)nimg * NPIXP
                                       + (size_t)(S * ay) * PITCH + (S * ax)) * CPT;
    const uint32_t sAo = (uint32_t)((ar * SSTR + ach) * 2);

    // B loader: 192 rows x 8 chunks = 1536 slots; slots tid, tid+512, tid+1024.
    const unsigned short* Bg0 = Bg + (size_t)co0 * K;
    int boff[3];
    uint32_t sBoj[3];
#pragma unroll
    for (int j = 0; j < 3; j++) {
        int slot = tid + j * 512;
        int br = slot >> 3;                       // 0..191
        int bc = (slot & 7) * 8;                  // u16 offset
        boff[j] = br * K + bc;
        sBoj[j] = (uint32_t)((br * SSTR + bc) * 2);
    }

    // ldmatrix per-thread byte offsets within plane
    const uint32_t offA = (uint32_t)(((wm * 32 + (lane & 15)) * SSTR + 8 * (lane >> 4)) * 2);
    const uint32_t offB = (uint32_t)(((wn * 48 + (lane & 7) + 8 * (lane >> 4)) * SSTR
                                      + 8 * ((lane >> 3) & 1)) * 2);

    float acc[2][6][4];
#pragma unroll
    for (int a = 0; a < 2; a++)
#pragma unroll
        for (int b = 0; b < 6; b++)
#pragma unroll
            for (int c = 0; c < 4; c++) acc[a][b][c] = 0.f;

#define ISSUE(t_)                                                              \
    do {                                                                       \
        int t__ = (t_);                                                        \
        if (t__ < T) {                                                         \
            const uint32_t sb = smem_b + (uint32_t)((t__ & 1) * STG) * 2;      \
            const int tap__ = t__ / CPT64;                                     \
            const int rem__ = t__ - tap__ * CPT64;                             \
            const int ky__  = tap__ / 3;                                       \
            const int kx__  = tap__ - ky__ * 3;                                \
            const int poff__ = (ky__ * PITCH + kx__) * CPT + rem__ * BK + ach; \
            cp16(sb + sAo,                rowH + poff__);                      \
            cp16(sb + sAo + 16,           rowH + poff__ + 8);                  \
            cp16(sb + A_SZ * 2 + sAo,      rowL + poff__);                     \
            cp16(sb + A_SZ * 2 + sAo + 16, rowL + poff__ + 8);                 \
            const int kt__ = t__ * BK;                                         \
            _Pragma("unroll")                                                  \
            for (int j = 0; j < 3; j++)                                        \
                cp16(sb + 2 * A_SZ * 2 + sBoj[j], Bg0 + boff[j] + kt__);       \
        }                                                                      \
        cp_commit();                                                           \
    } while (0)

    ISSUE(0);
    ISSUE(1);

    for (int t = 0; t < T; t++) {
        cp_wait1();
        __syncthreads();

        const uint32_t aH = smem_b + (uint32_t)((t & 1) * STG) * 2;
        const uint32_t aL = aH + A_SZ * 2;
        const uint32_t bH = aH + 2 * A_SZ * 2;

#pragma unroll
        for (int h = 0; h < BK; h += 16) {
            uint32_t Af[2][4], Lf[2][4], Bf[6][2];

            // ---- A_hi + B loads, then hi*B mmas ----
#pragma unroll
            for (int mi = 0; mi < 2; mi++) {
                const uint32_t d = offA + (uint32_t)((mi * 16 * SSTR + h) * 2);
                ldmx4(Af[mi][0], Af[mi][1], Af[mi][2], Af[mi][3], aH + d);
            }
#pragma unroll
            for (int np = 0; np < 3; np++) {
                const uint32_t d = offB + (uint32_t)((np * 16 * SSTR + h) * 2);
                ldmx4(Bf[2*np][0], Bf[2*np][1], Bf[2*np+1][0], Bf[2*np+1][1], bH + d);
            }
#pragma unroll
            for (int mi = 0; mi < 2; mi++)
#pragma unroll
                for (int ni = 0; ni < 6; ni++)
                    mma_f16(acc[mi][ni][0], acc[mi][ni][1], acc[mi][ni][2], acc[mi][ni][3],
                            Af[mi][0], Af[mi][1], Af[mi][2], Af[mi][3],
                            Bf[ni][0], Bf[ni][1]);

            // ---- A_lo loads overlap, then lo*B mmas ----
#pragma unroll
            for (int mi = 0; mi < 2; mi++) {
                const uint32_t d = offA + (uint32_t)((mi * 16 * SSTR + h) * 2);
                ldmx4(Lf[mi][0], Lf[mi][1], Lf[mi][2], Lf[mi][3], aL + d);
            }
#pragma unroll
            for (int mi = 0; mi < 2; mi++)
#pragma unroll
                for (int ni = 0; ni < 6; ni++)
                    mma_f16(acc[mi][ni][0], acc[mi][ni][1], acc[mi][ni][2], acc[mi][ni][3],
                            Lf[mi][0], Lf[mi][1], Lf[mi][2], Lf[mi][3],
                            Bf[ni][0], Bf[ni][1]);
        }

        __syncthreads();      // all warps done reading stage t
        ISSUE(t + 2);         // safe to overwrite buffer (t & 1)
    }
#undef ISSUE

    // ---- epilogue: stage acc in smem, then coalesced NCHW writes ----
    __syncthreads();
    float* sOut = reinterpret_cast<float*>(smem);   // [co][129] padded, 99072 B
#pragma unroll
    for (int mi = 0; mi < 2; mi++) {
#pragma unroll
        for (int half = 0; half < 2; half++) {
            int ml = wm * 32 + mi * 16 + grp + 8 * half;
#pragma unroll
            for (int ni = 0; ni < 6; ni++) {
                int cl = wn * 48 + ni * 8 + 2 * tg;
                sOut[cl * 129 + ml]       = acc[mi][ni][2 * half];
                sOut[(cl + 1) * 129 + ml] = acc[mi][ni][2 * half + 1];
            }
        }
    }
    __syncthreads();
    for (int idx = tid; idx < BN * BM; idx += 512) {
        int cl = idx >> 7;            // 0..191
        int ml = idx & 127;           // consecutive m for consecutive tid
        int m  = m0 + ml;
        int nimg2 = m / PIX;
        int pix2  = m - nimg2 * PIX;
        int co = co0 + cl;
        out[((size_t)nimg2 * NCO + co) * PIX + pix2] = sOut[cl * 129 + ml] + __ldg(&bias[co]);
    }
}

// ---------------------------------------------------------------------------
// GroupNorm + affine + ReLU (in-place fp32 NCHW) + NHWC fp16 hi/lo repack.
// Optionally mirrors normalized output into `outc` (last layer -> d_out).
// ---------------------------------------------------------------------------
__global__ void __launch_bounds__(256) gn_relu_pack_kernel(
    float* __restrict__ buf, const float* __restrict__ sc, const float* __restrict__ bi,
    unsigned short* __restrict__ ph, unsigned short* __restrict__ pl,
    float* __restrict__ outc)
{
    const int blk = blockIdx.x;
    const int n   = blk / NGROUP;
    const int g   = blk - n * NGROUP;
    float* base = buf + (size_t)blk * GSZ;
    const int tid = threadIdx.x;

    __shared__ float s_vals[GSZ];
    __shared__ float r1[8], r2[8];
    __shared__ float s_mu, s_inv;

    float vals[4];
    int cnt = 0;
    float s1 = 0.f, s2 = 0.f;
    for (int e = tid; e < GSZ; e += 256) {
        float x = base[e];
        vals[cnt++] = x;
        s1 += x; s2 += x * x;
    }
#pragma unroll
    for (int o = 16; o > 0; o >>= 1) {
        s1 += __shfl_xor_sync(0xffffffff, s1, o);
        s2 += __shfl_xor_sync(0xffffffff, s2, o);
    }
    const int w = tid >> 5, lane = tid & 31;
    if (lane == 0) { r1[w] = s1; r2[w] = s2; }
    __syncthreads();
    if (tid == 0) {
        float a = 0.f, b = 0.f;
#pragma unroll
        for (int i = 0; i < 8; i++) { a += r1[i]; b += r2[i]; }
        float mu  = a * (1.f / GSZ);
        float var = b * (1.f / GSZ) - mu * mu;
        s_mu = mu;
        s_inv = rsqrtf(var + 1e-5f);
    }
    __syncthreads();
    const float mu = s_mu, inv = s_inv;
    cnt = 0;
    for (int e = tid; e < GSZ; e += 256) {
        const int chl = e / PIX;
        const int ch  = g * 16 + chl;
        float y = (vals[cnt++] - mu) * inv * sc[ch] + bi[ch];
        y = fmaxf(y, 0.f);
        base[e] = y;
        s_vals[e] = y;
        if (outc) outc[(size_t)blk * GSZ + e] = y;
    }
    __syncthreads();

    if (tid < PIX) {
        const int py = tid / OHW, px = tid - py * OHW;
        uint32_t hw[8], lw[8];
#pragma unroll
        for (int j = 0; j < 8; j++) {
            unsigned short h0, l0, h1, l1;
            split_f16(s_vals[(2 * j) * PIX + tid], h0, l0);
            split_f16(s_vals[(2 * j + 1) * PIX + tid], h1, l1);
            hw[j] = (uint32_t)h0 | ((uint32_t)h1 << 16);
            lw[j] = (uint32_t)l0 | ((uint32_t)l1 << 16);
        }
        size_t o = ((size_t)(n * 81) + (py + 1) * 9 + (px + 1)) * NCO + g * 16;
        *(uint4*)(ph + o)     = make_uint4(hw[0], hw[1], hw[2], hw[3]);
        *(uint4*)(ph + o + 8) = make_uint4(hw[4], hw[5], hw[6], hw[7]);
        *(uint4*)(pl + o)     = make_uint4(lw[0], lw[1], lw[2], lw[3]);
        *(uint4*)(pl + o + 8) = make_uint4(lw[4], lw[5], lw[6], lw[7]);
    }
}

// ---------------------------------------------------------------------------
// Message passing, dst-major (unchanged, fp32).
// ---------------------------------------------------------------------------
__global__ void __launch_bounds__(256) msg_pass_kernel(
    const float* __restrict__ src_feat, const float* __restrict__ pts,
    const float* __restrict__ dw_w, const float* __restrict__ dw_b,
    const float* __restrict__ pw_w, const float* __restrict__ pw_b,
    float* __restrict__ outp)
{
    const int n = blockIdx.x;
    const int p = blockIdx.y;
    const int tid = threadIdx.x;

    __shared__ float s_in[NC * PIX];
    __shared__ float s_dw[NC * PIX];
    __shared__ float s_pw[NC * NC];

    float racc[13];
    const float* ptsb = pts + (size_t)(n * NCO + p * NC) * PIX;
#pragma unroll
    for (int k = 0; k < 13; k++) {
        int i = tid + k * 256;
        if (i < NC * PIX) racc[k] = ptsb[i];
    }

    const int e0 = c_estart[p], e1 = c_estart[p + 1];
    for (int ed = e0; ed < e1; ed++) {
        const int q = c_esrc[ed];
        const float* sb = src_feat + (size_t)(n * NCO + q * NC) * PIX;
        for (int i = tid; i < NC * PIX; i += 256) s_in[i] = sb[i];
        for (int i = tid; i < NC * NC; i += 256) s_pw[i] = pw_w[ed * NC * NC + i];
        __syncthreads();

        for (int i = tid; i < NC * PIX; i += 256) {
            const int c = i / PIX;
            const int pix = i - c * PIX;
            const int y = pix / OHW, x = pix - y * OHW;
            const float* wv = dw_w + (ed * NC + c) * 25;
            float a = dw_b[ed * NC + c];
#pragma unroll
            for (int dy = 0; dy < 5; dy++) {
                const int yy = y + dy - 2;
                if ((unsigned)yy < (unsigned)OHW) {
#pragma unroll
                    for (int dx = 0; dx < 5; dx++) {
                        const int xx = x + dx - 2;
                        if ((unsigned)xx < (unsigned)OHW)
                            a += wv[dy * 5 + dx] * s_in[c * PIX + yy * OHW + xx];
                    }
                }
            }
            s_dw[i] = a;
        }
        __syncthreads();

#pragma unroll
        for (int k = 0; k < 13; k++) {
            const int i = tid + k * 256;
            if (i < NC * PIX) {
                const int o = i / PIX;
                const int pix = i - o * PIX;
                float a = pw_b[ed * NC + o];
                const float* wr = &s_pw[o * NC];
#pragma unroll 8
                for (int ic = 0; ic < NC; ic++) a += wr[ic] * s_dw[ic * PIX + pix];
                racc[k] += a;
            }
        }
        __syncthreads();
    }

    float* ob = outp + (size_t)(n * NCO + p * NC) * PIX;
#pragma unroll
    for (int k = 0; k < 13; k++) {
        int i = tid + k * 256;
        if (i < NC * PIX) ob[i] = racc[k];
    }
}

// ---------------------------------------------------------------------------
extern "C" void kernel_launch(void* const* d_in, const int* in_sizes, int n_in,
                              void* d_out, int out_size)
{
    const float* x       = (const float*)d_in[0];
    const float* conv0_w = (const float*)d_in[1];
    const float* conv0_b = (const float*)d_in[2];
    const float* gn0_s   = (const float*)d_in[3];
    const float* gn0_b   = (const float*)d_in[4];
    const float* convs_w = (const float*)d_in[5];
    const float* convs_b = (const float*)d_in[6];
    const float* gns_s   = (const float*)d_in[7];
    const float* gns_b   = (const float*)d_in[8];
    const float* fo_dw_w = (const float*)d_in[9];
    const float* fo_dw_b = (const float*)d_in[10];
    const float* fo_pw_w = (const float*)d_in[11];
    const float* fo_pw_b = (const float*)d_in[12];
    const float* so_dw_w = (const float*)d_in[13];
    const float* so_dw_b = (const float*)d_in[14];
    const float* so_pw_w = (const float*)d_in[15];
    const float* so_pw_b = (const float*)d_in[16];
    float* out = (float*)d_out;

    float *pA, *pB;
    unsigned short *pActH, *pActL, *pX0H, *pX0L, *pW0H, *pWrH;
    cudaGetSymbolAddress((void**)&pA,    g_bufA);
    cudaGetSymbolAddress((void**)&pB,    g_bufB);
    cudaGetSymbolAddress((void**)&pActH, g_acth);
    cudaGetSymbolAddress((void**)&pActL, g_actl);
    cudaGetSymbolAddress((void**)&pX0H,  g_x0h);
    cudaGetSymbolAddress((void**)&pX0L,  g_x0l);
    cudaGetSymbolAddress((void**)&pW0H,  g_w0h);
    cudaGetSymbolAddress((void**)&pWrH,  g_wrh);

    const int SMEM_CONV = 2 * (2 * BM * SSTR + BN * SSTR) * 2;   // 129024 B
    cudaFuncSetAttribute((const void*)conv_gemm_kernel<CIN0, 16, 2, KG0>,
                         cudaFuncAttributeMaxDynamicSharedMemorySize, SMEM_CONV);
    cudaFuncSetAttribute((const void*)conv_gemm_kernel<NCO, 9, 1, KGR>,
                         cudaFuncAttributeMaxDynamicSharedMemorySize, SMEM_CONV);

    // 1) pack inputs & weights (NHWC / tap-major), coalesced
    pack_x0_kernel<<<dim3(NROI, CIN0 / 32), 256>>>(x);
    pack_w0_kernel<<<(NCO * CIN0) / 256, 256>>>(conv0_w);
    pack_wr_kernel<<<(NREST * NCO * NCO) / 256, 256>>>(convs_w);

    dim3 cgrid(NCO / BN, MTOT / BM);   // (3, 196): co fastest -> A L2 reuse

    // 2) conv0 (stride 2) + GN0/ReLU(+repack)
    conv_gemm_kernel<CIN0, 16, 2, KG0><<<cgrid, 512, SMEM_CONV>>>(
        pX0H, pX0L, pW0H, conv0_b, pA);
    gn_relu_pack_kernel<<<NROI * NGROUP, 256>>>(pA, gn0_s, gn0_b, pActH, pActL, nullptr);

    // 3) 7x [conv + GN/ReLU(+repack)], ping-pong; last GN also writes out
    float* cur = pA;
    float* nxt = pB;
    for (int l = 0; l < NREST; l++) {
        conv_gemm_kernel<NCO, 9, 1, KGR><<<cgrid, 512, SMEM_CONV>>>(
            pActH, pActL, pWrH + (size_t)l * NCO * KGR, convs_b + l * NCO, nxt);
        gn_relu_pack_kernel<<<NROI * NGROUP, 256>>>(
            nxt, gns_s + l * NCO, gns_b + l * NCO, pActH, pActL,
            (l == NREST - 1) ? out : nullptr);
        float* t = cur; cur = nxt; nxt = t;
    }
    // cur == final h (already mirrored into out half 1), nxt free

    // 4) first-order fusion -> nxt
    dim3 mgrid(NROI, NP);
    msg_pass_kernel<<<mgrid, 256>>>(cur, cur, fo_dw_w, fo_dw_b, fo_pw_w, fo_pw_b, nxt);

    // 5) second-order fusion -> output half 2
    msg_pass_kernel<<<mgrid, 256>>>(nxt, cur, so_dw_w, so_dw_b, so_pw_w, so_pw_b,
                                    out + HALF_OUT);
}

// round 17
// speedup vs baseline: 1.4603x; 1.0605x over previous
#include <cuda_runtime.h>
#include <cuda_fp16.h>
#include <cstdint>

// ---------------------------------------------------------------------------
// roi_grid_head, round 15: fp16 2-stream split GEMM (A=Ah+Al fp16, B fp16;
// D = Ah*B + Al*B, fp32 accum) with 3-stage cp.async and a SINGLE
// __syncthreads per k-stage (buffer t+2 disjoint from buffer t).
// BM128xBN192, BK=64, 512 thr, 4m x 4n warps (32x48), staged epilogue,
// fused GN tail.
// ---------------------------------------------------------------------------

#define NROI   512
#define CIN0   256
#define OHW    7
#define PIX    49
#define NCO    576
#define NP     9
#define NC     64
#define NREST  7
#define KG0    (CIN0 * 9)            // 2304
#define KGR    (NCO * 9)             // 5184
#define MTOT   (NROI * PIX)          // 25088 = 196*128
#define NGROUP 36
#define GSZ    784
#define HALF_OUT (NROI * NCO * PIX)  // 14450688

#define BM 128
#define BN 192
#define BK 64
#define SSTR 72                       // smem row stride in fp16 units (144B)

// __device__ scratch (zero-initialized; padded border pixels never written)
__device__ unsigned short g_acth[NROI * 81 * NCO];    // act hi [n][9x9 pad][576]
__device__ unsigned short g_actl[NROI * 81 * NCO];    // act lo
__device__ unsigned short g_x0h[NROI * 256 * CIN0];   // x hi [n][16x16 pad][256]
__device__ unsigned short g_x0l[NROI * 256 * CIN0];
__device__ unsigned short g_w0h[NCO * KG0];           // conv0 W fp16 [co][tap*256+ci]
__device__ unsigned short g_wrh[NREST * NCO * KGR];   // convs W fp16
__device__ float g_bufA[HALF_OUT];
__device__ float g_bufB[HALF_OUT];

__constant__ int c_esrc[24]   = {1,3, 0,2,4, 1,5, 0,4,6, 1,3,5,7, 2,4,8, 3,7, 4,6,8, 5,7};
__constant__ int c_estart[10] = {0,2,5,7,10,14,17,19,22,24};

// ---------------------------------------------------------------------------
__device__ __forceinline__ void split_f16(float f, unsigned short& h, unsigned short& l) {
    __half hh = __float2half(f);
    float r = f - __half2float(hh);
    h = __half_as_ushort(hh);
    l = __half_as_ushort(__float2half(r));
}

__device__ __forceinline__ unsigned short to_f16(float f) {
    return __half_as_ushort(__float2half(f));
}

__device__ __forceinline__ void mma_f16(float& c0, float& c1, float& c2, float& c3,
                                        uint32_t a0, uint32_t a1, uint32_t a2, uint32_t a3,
                                        uint32_t b0, uint32_t b1) {
    asm volatile(
        "mma.sync.aligned.m16n8k16.row.col.f32.f16.f16.f32 "
        "{%0,%1,%2,%3},{%4,%5,%6,%7},{%8,%9},{%0,%1,%2,%3};\n"
        : "+f"(c0), "+f"(c1), "+f"(c2), "+f"(c3)
        : "r"(a0), "r"(a1), "r"(a2), "r"(a3), "r"(b0), "r"(b1));
}

__device__ __forceinline__ void ldmx4(uint32_t& r0, uint32_t& r1, uint32_t& r2, uint32_t& r3,
                                      uint32_t addr) {
    asm volatile("ldmatrix.sync.aligned.m8n8.x4.shared.b16 {%0,%1,%2,%3},[%4];\n"
                 : "=r"(r0), "=r"(r1), "=r"(r2), "=r"(r3) : "r"(addr));
}

__device__ __forceinline__ void cp16(uint32_t daddr, const void* src) {
    asm volatile("cp.async.cg.shared.global [%0], [%1], 16;\n" :: "r"(daddr), "l"(src));
}
__device__ __forceinline__ void cp_commit() { asm volatile("cp.async.commit_group;\n" ::: "memory"); }
__device__ __forceinline__ void cp_wait1()  { asm volatile("cp.async.wait_group 1;\n" ::: "memory"); }

// ---------------------------------------------------------------------------
// Packing kernels
// ---------------------------------------------------------------------------
__global__ void __launch_bounds__(256) pack_x0_kernel(const float* __restrict__ x) {
    __shared__ float sx[32 * 196];
    const int n  = blockIdx.x;
    const int c0 = blockIdx.y * 32;
    const int tid = threadIdx.x;
    for (int idx = tid; idx < 32 * 196; idx += 256) {
        int c = idx / 196, pix = idx - c * 196;
        sx[idx] = x[((size_t)(n * CIN0 + c0 + c)) * 196 + pix];
    }
    __syncthreads();
    for (int idx = tid; idx < 196 * 32; idx += 256) {
        int pix = idx >> 5, cl = idx & 31;
        int y = pix / 14, xx = pix - y * 14;
        unsigned short h, l;
        split_f16(sx[cl * 196 + pix], h, l);
        size_t o = ((size_t)(n * 256) + (y + 1) * 16 + (xx + 1)) * CIN0 + c0 + cl;
        g_x0h[o] = h; g_x0l[o] = l;
    }
}

__global__ void __launch_bounds__(256) pack_w0_kernel(const float* __restrict__ w) {
    int i = blockIdx.x * 256 + threadIdx.x;       // NCO*CIN0
    int co = i / CIN0, ci = i - co * CIN0;
    const float* wp = w + ((size_t)(co * CIN0 + ci)) * 9;
    size_t ob = (size_t)co * KG0 + ci;
#pragma unroll
    for (int tap = 0; tap < 9; tap++)
        g_w0h[ob + (size_t)tap * CIN0] = to_f16(wp[tap]);
}

__global__ void __launch_bounds__(256) pack_wr_kernel(const float* __restrict__ w) {
    int i = blockIdx.x * 256 + threadIdx.x;       // NREST*NCO*NCO
    int l = i / (NCO * NCO);
    int r = i - l * (NCO * NCO);
    int co = r / NCO, ci = r - co * NCO;
    const float* wp = w + ((size_t)(l * NCO + co) * NCO + ci) * 9;
    size_t ob = (size_t)(l * NCO + co) * KGR + ci;
#pragma unroll
    for (int tap = 0; tap < 9; tap++)
        g_wrh[ob + (size_t)tap * NCO] = to_f16(wp[tap]);
}

// ---------------------------------------------------------------------------
// NHWC implicit-GEMM conv, fp16 2-stream, 3-stage, one barrier per stage.
// ---------------------------------------------------------------------------
template<int CPT, int PITCH, int S, int K>
__global__ void __launch_bounds__(512, 1) conv_gemm_kernel(
    const unsigned short* __restrict__ Ah, const unsigned short* __restrict__ Al,
    const unsigned short* __restrict__ Bg,
    const float* __restrict__ bias, float* __restrict__ out)
{
    extern __shared__ unsigned short smem[];
    constexpr int A_SZ  = BM * SSTR;              // 9216 u16
    constexpr int B_SZ  = BN * SSTR;              // 13824 u16
    constexpr int STG   = 2 * A_SZ + B_SZ;        // 32256 u16 = 64512 B
    constexpr int T     = K / BK;
    constexpr int CPT64 = CPT / BK;
    constexpr int NPIXP = PITCH * PITCH;

    const int tid  = threadIdx.x;
    const int lane = tid & 31;
    const int warp = tid >> 5;
    const int wm = warp >> 2, wn = warp & 3;      // 4 x 4 warp grid
    const int grp = lane >> 2, tg = lane & 3;
    const int co0 = blockIdx.x * BN;
    const int m0  = blockIdx.y * BM;

    const uint32_t smem_b = (uint32_t)__cvta_generic_to_shared(smem);

    // A loader: 128 rows x 4 chunks of 32 u16 (2 cp16 each); slot = tid.
    const int ar  = tid >> 2;                     // 0..127
    const int ach = (tid & 3) * 16;               // u16 offset {0,16,32,48}
    const int am   = m0 + ar;
    const int nimg = am / PIX;
    const int apix = am - nimg * PIX;
    const int ay   = apix / OHW, ax = apix - ay * OHW;
    const unsigned short* rowH = Ah + ((size_t)nimg * NPIXP
                                       + (size_t)(S * ay) * PITCH + (S * ax)) * CPT;
    const unsigned short* rowL = Al + ((size_t)nimg * NPIXP
                                       + (size_t)(S * ay) * PITCH + (S * ax)) * CPT;
    const uint32_t sAo = (uint32_t)((ar * SSTR + ach) * 2);

    // B loader: 192 rows x 8 chunks = 1536 slots; slots tid, tid+512, tid+1024.
    const unsigned short* Bg0 = Bg + (size_t)co0 * K;
    int boff[3];
    uint32_t sBoj[3];
#pragma unroll
    for (int j = 0; j < 3; j++) {
        int slot = tid + j * 512;
        int br = slot >> 3;                       // 0..191
        int bc = (slot & 7) * 8;                  // u16 offset
        boff[j] = br * K + bc;
        sBoj[j] = (uint32_t)((br * SSTR + bc) * 2);
    }

    // ldmatrix per-thread byte offsets within plane
    const uint32_t offA = (uint32_t)(((wm * 32 + (lane & 15)) * SSTR + 8 * (lane >> 4)) * 2);
    const uint32_t offB = (uint32_t)(((wn * 48 + (lane & 7) + 8 * (lane >> 4)) * SSTR
                                      + 8 * ((lane >> 3) & 1)) * 2);

    float acc[2][6][4];
#pragma unroll
    for (int a = 0; a < 2; a++)
#pragma unroll
        for (int b = 0; b < 6; b++)
#pragma unroll
            for (int c = 0; c < 4; c++) acc[a][b][c] = 0.f;

#define ISSUE(t_)                                                              \
    do {                                                                       \
        int t__ = (t_);                                                        \
        if (t__ < T) {                                                         \
            const uint32_t sb = smem_b + (uint32_t)((t__ % 3) * STG) * 2;      \
            const int tap__ = t__ / CPT64;                                     \
            const int rem__ = t__ - tap__ * CPT64;                             \
            const int ky__  = tap__ / 3;                                       \
            const int kx__  = tap__ - ky__ * 3;                                \
            const int poff__ = (ky__ * PITCH + kx__) * CPT + rem__ * BK + ach; \
            cp16(sb + sAo,                rowH + poff__);                      \
            cp16(sb + sAo + 16,           rowH + poff__ + 8);                  \
            cp16(sb + A_SZ * 2 + sAo,      rowL + poff__);                     \
            cp16(sb + A_SZ * 2 + sAo + 16, rowL + poff__ + 8);                 \
            const int kt__ = t__ * BK;                                         \
            _Pragma("unroll")                                                  \
            for (int j = 0; j < 3; j++)                                        \
                cp16(sb + 2 * A_SZ * 2 + sBoj[j], Bg0 + boff[j] + kt__);       \
        }                                                                      \
        cp_commit();                                                           \
    } while (0)

    ISSUE(0);
    ISSUE(1);

    for (int t = 0; t < T; t++) {
        cp_wait1();
        __syncthreads();      // stage t ready; everyone done reading stage t-1
        ISSUE(t + 2);         // writes buffer (t+2)%3 == (t-1)%3 — safe now

        const uint32_t aH = smem_b + (uint32_t)((t % 3) * STG) * 2;
        const uint32_t aL = aH + A_SZ * 2;
        const uint32_t bH = aH + 2 * A_SZ * 2;

#pragma unroll
        for (int h = 0; h < BK; h += 16) {
            uint32_t Af[2][4], Lf[2][4], Bf[6][2];

            // ---- A_hi + B loads, then hi*B mmas ----
#pragma unroll
            for (int mi = 0; mi < 2; mi++) {
                const uint32_t d = offA + (uint32_t)((mi * 16 * SSTR + h) * 2);
                ldmx4(Af[mi][0], Af[mi][1], Af[mi][2], Af[mi][3], aH + d);
            }
#pragma unroll
            for (int np = 0; np < 3; np++) {
                const uint32_t d = offB + (uint32_t)((np * 16 * SSTR + h) * 2);
                ldmx4(Bf[2*np][0], Bf[2*np][1], Bf[2*np+1][0], Bf[2*np+1][1], bH + d);
            }
#pragma unroll
            for (int mi = 0; mi < 2; mi++)
#pragma unroll
                for (int ni = 0; ni < 6; ni++)
                    mma_f16(acc[mi][ni][0], acc[mi][ni][1], acc[mi][ni][2], acc[mi][ni][3],
                            Af[mi][0], Af[mi][1], Af[mi][2], Af[mi][3],
                            Bf[ni][0], Bf[ni][1]);

            // ---- A_lo loads overlap, then lo*B mmas ----
#pragma unroll
            for (int mi = 0; mi < 2; mi++) {
                const uint32_t d = offA + (uint32_t)((mi * 16 * SSTR + h) * 2);
                ldmx4(Lf[mi][0], Lf[mi][1], Lf[mi][2], Lf[mi][3], aL + d);
            }
#pragma unroll
            for (int mi = 0; mi < 2; mi++)
#pragma unroll
                for (int ni = 0; ni < 6; ni++)
                    mma_f16(acc[mi][ni][0], acc[mi][ni][1], acc[mi][ni][2], acc[mi][ni][3],
                            Lf[mi][0], Lf[mi][1], Lf[mi][2], Lf[mi][3],
                            Bf[ni][0], Bf[ni][1]);
        }
    }
#undef ISSUE

    // ---- epilogue: stage acc in smem, then coalesced NCHW writes ----
    __syncthreads();
    float* sOut = reinterpret_cast<float*>(smem);   // [co][129] padded, 99072 B
#pragma unroll
    for (int mi = 0; mi < 2; mi++) {
#pragma unroll
        for (int half = 0; half < 2; half++) {
            int ml = wm * 32 + mi * 16 + grp + 8 * half;
#pragma unroll
            for (int ni = 0; ni < 6; ni++) {
                int cl = wn * 48 + ni * 8 + 2 * tg;
                sOut[cl * 129 + ml]       = acc[mi][ni][2 * half];
                sOut[(cl + 1) * 129 + ml] = acc[mi][ni][2 * half + 1];
            }
        }
    }
    __syncthreads();
    for (int idx = tid; idx < BN * BM; idx += 512) {
        int cl = idx >> 7;            // 0..191
        int ml = idx & 127;           // consecutive m for consecutive tid
        int m  = m0 + ml;
        int nimg2 = m / PIX;
        int pix2  = m - nimg2 * PIX;
        int co = co0 + cl;
        out[((size_t)nimg2 * NCO + co) * PIX + pix2] = sOut[cl * 129 + ml] + __ldg(&bias[co]);
    }
}

// ---------------------------------------------------------------------------
// GroupNorm + affine + ReLU (in-place fp32 NCHW) + NHWC fp16 hi/lo repack.
// Optionally mirrors normalized output into `outc` (last layer -> d_out).
// ---------------------------------------------------------------------------
__global__ void __launch_bounds__(256) gn_relu_pack_kernel(
    float* __restrict__ buf, const float* __restrict__ sc, const float* __restrict__ bi,
    unsigned short* __restrict__ ph, unsigned short* __restrict__ pl,
    float* __restrict__ outc)
{
    const int blk = blockIdx.x;
    const int n   = blk / NGROUP;
    const int g   = blk - n * NGROUP;
    float* base = buf + (size_t)blk * GSZ;
    const int tid = threadIdx.x;

    __shared__ float s_vals[GSZ];
    __shared__ float r1[8], r2[8];
    __shared__ float s_mu, s_inv;

    float vals[4];
    int cnt = 0;
    float s1 = 0.f, s2 = 0.f;
    for (int e = tid; e < GSZ; e += 256) {
        float x = base[e];
        vals[cnt++] = x;
        s1 += x; s2 += x * x;
    }
#pragma unroll
    for (int o = 16; o > 0; o >>= 1) {
        s1 += __shfl_xor_sync(0xffffffff, s1, o);
        s2 += __shfl_xor_sync(0xffffffff, s2, o);
    }
    const int w = tid >> 5, lane = tid & 31;
    if (lane == 0) { r1[w] = s1; r2[w] = s2; }
    __syncthreads();
    if (tid == 0) {
        float a = 0.f, b = 0.f;
#pragma unroll
        for (int i = 0; i < 8; i++) { a += r1[i]; b += r2[i]; }
        float mu  = a * (1.f / GSZ);
        float var = b * (1.f / GSZ) - mu * mu;
        s_mu = mu;
        s_inv = rsqrtf(var + 1e-5f);
    }
    __syncthreads();
    const float mu = s_mu, inv = s_inv;
    cnt = 0;
    for (int e = tid; e < GSZ; e += 256) {
        const int chl = e / PIX;
        const int ch  = g * 16 + chl;
        float y = (vals[cnt++] - mu) * inv * sc[ch] + bi[ch];
        y = fmaxf(y, 0.f);
        base[e] = y;
        s_vals[e] = y;
        if (outc) outc[(size_t)blk * GSZ + e] = y;
    }
    __syncthreads();

    if (tid < PIX) {
        const int py = tid / OHW, px = tid - py * OHW;
        uint32_t hw[8], lw[8];
#pragma unroll
        for (int j = 0; j < 8; j++) {
            unsigned short h0, l0, h1, l1;
            split_f16(s_vals[(2 * j) * PIX + tid], h0, l0);
            split_f16(s_vals[(2 * j + 1) * PIX + tid], h1, l1);
            hw[j] = (uint32_t)h0 | ((uint32_t)h1 << 16);
            lw[j] = (uint32_t)l0 | ((uint32_t)l1 << 16);
        }
        size_t o = ((size_t)(n * 81) + (py + 1) * 9 + (px + 1)) * NCO + g * 16;
        *(uint4*)(ph + o)     = make_uint4(hw[0], hw[1], hw[2], hw[3]);
        *(uint4*)(ph + o + 8) = make_uint4(hw[4], hw[5], hw[6], hw[7]);
        *(uint4*)(pl + o)     = make_uint4(lw[0], lw[1], lw[2], lw[3]);
        *(uint4*)(pl + o + 8) = make_uint4(lw[4], lw[5], lw[6], lw[7]);
    }
}

// ---------------------------------------------------------------------------
// Message passing, dst-major (unchanged, fp32).
// ---------------------------------------------------------------------------
__global__ void __launch_bounds__(256) msg_pass_kernel(
    const float* __restrict__ src_feat, const float* __restrict__ pts,
    const float* __restrict__ dw_w, const float* __restrict__ dw_b,
    const float* __restrict__ pw_w, const float* __restrict__ pw_b,
    float* __restrict__ outp)
{
    const int n = blockIdx.x;
    const int p = blockIdx.y;
    const int tid = threadIdx.x;

    __shared__ float s_in[NC * PIX];
    __shared__ float s_dw[NC * PIX];
    __shared__ float s_pw[NC * NC];

    float racc[13];
    const float* ptsb = pts + (size_t)(n * NCO + p * NC) * PIX;
#pragma unroll
    for (int k = 0; k < 13; k++) {
        int i = tid + k * 256;
        if (i < NC * PIX) racc[k] = ptsb[i];
    }

    const int e0 = c_estart[p], e1 = c_estart[p + 1];
    for (int ed = e0; ed < e1; ed++) {
        const int q = c_esrc[ed];
        const float* sb = src_feat + (size_t)(n * NCO + q * NC) * PIX;
        for (int i = tid; i < NC * PIX; i += 256) s_in[i] = sb[i];
        for (int i = tid; i < NC * NC; i += 256) s_pw[i] = pw_w[ed * NC * NC + i];
        __syncthreads();

        for (int i = tid; i < NC * PIX; i += 256) {
            const int c = i / PIX;
            const int pix = i - c * PIX;
            const int y = pix / OHW, x = pix - y * OHW;
            const float* wv = dw_w + (ed * NC + c) * 25;
            float a = dw_b[ed * NC + c];
#pragma unroll
            for (int dy = 0; dy < 5; dy++) {
                const int yy = y + dy - 2;
                if ((unsigned)yy < (unsigned)OHW) {
#pragma unroll
                    for (int dx = 0; dx < 5; dx++) {
                        const int xx = x + dx - 2;
                        if ((unsigned)xx < (unsigned)OHW)
                            a += wv[dy * 5 + dx] * s_in[c * PIX + yy * OHW + xx];
                    }
                }
            }
            s_dw[i] = a;
        }
        __syncthreads();

#pragma unroll
        for (int k = 0; k < 13; k++) {
            const int i = tid + k * 256;
            if (i < NC * PIX) {
                const int o = i / PIX;
                const int pix = i - o * PIX;
                float a = pw_b[ed * NC + o];
                const float* wr = &s_pw[o * NC];
#pragma unroll 8
                for (int ic = 0; ic < NC; ic++) a += wr[ic] * s_dw[ic * PIX + pix];
                racc[k] += a;
            }
        }
        __syncthreads();
    }

    float* ob = outp + (size_t)(n * NCO + p * NC) * PIX;
#pragma unroll
    for (int k = 0; k < 13; k++) {
        int i = tid + k * 256;
        if (i < NC * PIX) ob[i] = racc[k];
    }
}

// ---------------------------------------------------------------------------
extern "C" void kernel_launch(void* const* d_in, const int* in_sizes, int n_in,
                              void* d_out, int out_size)
{
    const float* x       = (const float*)d_in[0];
    const float* conv0_w = (const float*)d_in[1];
    const float* conv0_b = (const float*)d_in[2];
    const float* gn0_s   = (const float*)d_in[3];
    const float* gn0_b   = (const float*)d_in[4];
    const float* convs_w = (const float*)d_in[5];
    const float* convs_b = (const float*)d_in[6];
    const float* gns_s   = (const float*)d_in[7];
    const float* gns_b   = (const float*)d_in[8];
    const float* fo_dw_w = (const float*)d_in[9];
    const float* fo_dw_b = (const float*)d_in[10];
    const float* fo_pw_w = (const float*)d_in[11];
    const float* fo_pw_b = (const float*)d_in[12];
    const float* so_dw_w = (const float*)d_in[13];
    const float* so_dw_b = (const float*)d_in[14];
    const float* so_pw_w = (const float*)d_in[15];
    const float* so_pw_b = (const float*)d_in[16];
    float* out = (float*)d_out;

    float *pA, *pB;
    unsigned short *pActH, *pActL, *pX0H, *pX0L, *pW0H, *pWrH;
    cudaGetSymbolAddress((void**)&pA,    g_bufA);
    cudaGetSymbolAddress((void**)&pB,    g_bufB);
    cudaGetSymbolAddress((void**)&pActH, g_acth);
    cudaGetSymbolAddress((void**)&pActL, g_actl);
    cudaGetSymbolAddress((void**)&pX0H,  g_x0h);
    cudaGetSymbolAddress((void**)&pX0L,  g_x0l);
    cudaGetSymbolAddress((void**)&pW0H,  g_w0h);
    cudaGetSymbolAddress((void**)&pWrH,  g_wrh);

    const int SMEM_CONV = 3 * (2 * BM * SSTR + BN * SSTR) * 2;   // 193536 B
    cudaFuncSetAttribute((const void*)conv_gemm_kernel<CIN0, 16, 2, KG0>,
                         cudaFuncAttributeMaxDynamicSharedMemorySize, SMEM_CONV);
    cudaFuncSetAttribute((const void*)conv_gemm_kernel<NCO, 9, 1, KGR>,
                         cudaFuncAttributeMaxDynamicSharedMemorySize, SMEM_CONV);

    // 1) pack inputs & weights (NHWC / tap-major), coalesced
    pack_x0_kernel<<<dim3(NROI, CIN0 / 32), 256>>>(x);
    pack_w0_kernel<<<(NCO * CIN0) / 256, 256>>>(conv0_w);
    pack_wr_kernel<<<(NREST * NCO * NCO) / 256, 256>>>(convs_w);

    dim3 cgrid(NCO / BN, MTOT / BM);   // (3, 196): co fastest -> A L2 reuse

    // 2) conv0 (stride 2) + GN0/ReLU(+repack)
    conv_gemm_kernel<CIN0, 16, 2, KG0><<<cgrid, 512, SMEM_CONV>>>(
        pX0H, pX0L, pW0H, conv0_b, pA);
    gn_relu_pack_kernel<<<NROI * NGROUP, 256>>>(pA, gn0_s, gn0_b, pActH, pActL, nullptr);

    // 3) 7x [conv + GN/ReLU(+repack)], ping-pong; last GN also writes out
    float* cur = pA;
    float* nxt = pB;
    for (int l = 0; l < NREST; l++) {
        conv_gemm_kernel<NCO, 9, 1, KGR><<<cgrid, 512, SMEM_CONV>>>(
            pActH, pActL, pWrH + (size_t)l * NCO * KGR, convs_b + l * NCO, nxt);
        gn_relu_pack_kernel<<<NROI * NGROUP, 256>>>(
            nxt, gns_s + l * NCO, gns_b + l * NCO, pActH, pActL,
            (l == NREST - 1) ? out : nullptr);
        float* t = cur; cur = nxt; nxt = t;
    }
    // cur == final h (already mirrored into out half 1), nxt free

    // 4) first-order fusion -> nxt
    dim3 mgrid(NROI, NP);
    msg_pass_kernel<<<mgrid, 256>>>(cur, cur, fo_dw_w, fo_dw_b, fo_pw_w, fo_pw_b, nxt);

    // 5) second-order fusion -> output half 2
    msg_pass_kernel<<<mgrid, 256>>>(nxt, cur, so_dw_w, so_dw_b, so_pw_w, so_pw_b,
                                    out + HALF_OUT);
}